// round 1
// baseline (speedup 1.0000x reference)
#include <cuda_runtime.h>
#include <cuda_bf16.h>
#include <math.h>

#define G 512
#define D 256
#define MAXN 204800

// ---------------- device scratch ----------------
__device__ float    g_Wc[1024 * 512];     // combined weight [4D x 2D]
__device__ float    g_biasc[1024];        // b_ih + b_hh
__device__ int      g_counts[G];
__device__ int      g_cursor[G];
__device__ int      g_perm[MAXN];         // node id sorted by graph
__device__ int      g_grank[MAXN];        // graph id per rank
__device__ float    g_e[MAXN];            // e, then exp(e-max)
__device__ float    g_xbuf[G * 512];      // q_star layout: [h | r] per graph
__device__ float    g_cbuf[G * D];        // LSTM cell state
__device__ float    g_gates[G * 1024];    // GEMM accumulator (zeroed between uses)
__device__ unsigned g_gmaxe[G];           // order-encoded float max
__device__ float    g_gsum[G];

// order-preserving float<->uint encoding for atomicMax
__device__ __forceinline__ unsigned fenc(float f) {
    unsigned u = __float_as_uint(f);
    return (u & 0x80000000u) ? ~u : (u | 0x80000000u);
}
__device__ __forceinline__ float fdec(unsigned u) {
    return (u & 0x80000000u) ? __uint_as_float(u ^ 0x80000000u)
                             : __uint_as_float(~u);
}
#define ENC_NEG_INF 0x007FFFFFu   // fenc(-inf)

__device__ __forceinline__ float sigf(float x) { return 1.0f / (1.0f + expf(-x)); }

// ---------------- prep: combined weights, bias, zero counts ----------------
__global__ void k_prep(const float* __restrict__ W_ih, const float* __restrict__ W_hh,
                       const float* __restrict__ b_ih, const float* __restrict__ b_hh) {
    int i = blockIdx.x * blockDim.x + threadIdx.x;
    if (i < 1024 * 512) {
        int j = i >> 9, k = i & 511;
        float w = W_ih[i];
        if (k < D) w += W_hh[j * D + k];
        g_Wc[i] = w;
    }
    if (i < 1024) g_biasc[i] = b_ih[i] + b_hh[i];
    if (i < G) g_counts[i] = 0;
}

// ---------------- counting sort of nodes by graph ----------------
__global__ void k_hist(const int* __restrict__ bidx, int N) {
    __shared__ int sh[G];
    for (int i = threadIdx.x; i < G; i += blockDim.x) sh[i] = 0;
    __syncthreads();
    for (int i = blockIdx.x * blockDim.x + threadIdx.x; i < N; i += gridDim.x * blockDim.x)
        atomicAdd(&sh[bidx[i]], 1);
    __syncthreads();
    for (int i = threadIdx.x; i < G; i += blockDim.x)
        if (sh[i]) atomicAdd(&g_counts[i], sh[i]);
}

__global__ void k_scan() {   // one block, 512 threads
    __shared__ int s[G];
    int t = threadIdx.x;
    s[t] = g_counts[t];
    __syncthreads();
    for (int o = 1; o < G; o <<= 1) {
        int v = 0;
        if (t >= o) v = s[t - o];
        __syncthreads();
        if (t >= o) s[t] += v;
        __syncthreads();
    }
    g_cursor[t] = s[t] - g_counts[t];   // exclusive prefix
}

__global__ void k_scatter(const int* __restrict__ bidx, int N) {
    int i = blockIdx.x * blockDim.x + threadIdx.x;
    if (i < N) {
        int g = bidx[i];
        int p = atomicAdd(&g_cursor[g], 1);
        g_perm[p] = i;
        g_grank[p] = g;
    }
}

// ---------------- step-1 LSTM: all state zero -> gates = bias ----------------
__global__ void k_cell0() {
    int idx = blockIdx.x * blockDim.x + threadIdx.x;   // < G*D
    int g = idx >> 8, d = idx & 255;
    float i_ = sigf(g_biasc[d]);
    float gg = tanhf(g_biasc[512 + d]);
    float o_ = sigf(g_biasc[768 + d]);
    float c = i_ * gg;
    float h = o_ * tanhf(c);
    g_cbuf[idx] = c;
    g_xbuf[g * 512 + d] = h;
    g_xbuf[g * 512 + D + d] = 0.0f;
    if (idx < G) { g_gmaxe[idx] = ENC_NEG_INF; g_gsum[idx] = 0.0f; }
#pragma unroll
    for (int k = 0; k < 4; k++) g_gates[idx * 4 + k] = 0.0f;   // zero full gates buffer
}

// ---------------- steps 2,3 LSTM cell (gates precomputed by GEMM) ----------------
__global__ void k_cellk() {
    int idx = blockIdx.x * blockDim.x + threadIdx.x;   // < G*D
    int g = idx >> 8, d = idx & 255;
    int base = g * 1024;
    float gi = g_gates[base + d]       + g_biasc[d];
    float gf = g_gates[base + 256 + d] + g_biasc[256 + d];
    float gg = g_gates[base + 512 + d] + g_biasc[512 + d];
    float go = g_gates[base + 768 + d] + g_biasc[768 + d];
    float i_ = sigf(gi), f_ = sigf(gf), gt = tanhf(gg), o_ = sigf(go);
    float c = f_ * g_cbuf[idx] + i_ * gt;
    float h = o_ * tanhf(c);
    g_cbuf[idx] = c;
    g_xbuf[g * 512 + d] = h;
    g_xbuf[g * 512 + D + d] = 0.0f;      // zero r accumulator
    // re-zero gates for the next GEMM's atomic accumulation
    g_gates[base + d] = 0.0f; g_gates[base + 256 + d] = 0.0f;
    g_gates[base + 512 + d] = 0.0f; g_gates[base + 768 + d] = 0.0f;
    if (idx < G) { g_gmaxe[idx] = ENC_NEG_INF; g_gsum[idx] = 0.0f; }
}

// ---------------- GEMM: gates += xbuf[512x512] @ Wc^T[512x1024], split-K=2 ----------------
#define BM 64
#define BN 64
#define BK 32
__global__ void __launch_bounds__(256) k_gemm() {
    __shared__ float As[BK][BM + 4];
    __shared__ float Bs[BK][BN + 4];
    int tid = threadIdx.x;
    int bm = blockIdx.y * BM;
    int bn = blockIdx.x * BN;
    int k0 = blockIdx.z * 256;
    int lr = tid >> 2;            // 0..63 tile row for loading
    int lc = (tid & 3) * 8;       // k offset 0,8,16,24
    int tm = (tid >> 4) * 4;      // compute micro-tile
    int tn = (tid & 15) * 4;
    float acc[4][4] = {};
    for (int kt = 0; kt < 256; kt += BK) {
        const float4* ap = (const float4*)(g_xbuf + (size_t)(bm + lr) * 512 + k0 + kt + lc);
        float4 a0 = ap[0], a1 = ap[1];
        const float4* bp = (const float4*)(g_Wc + (size_t)(bn + lr) * 512 + k0 + kt + lc);
        float4 b0 = bp[0], b1 = bp[1];
        __syncthreads();
        As[lc + 0][lr] = a0.x; As[lc + 1][lr] = a0.y; As[lc + 2][lr] = a0.z; As[lc + 3][lr] = a0.w;
        As[lc + 4][lr] = a1.x; As[lc + 5][lr] = a1.y; As[lc + 6][lr] = a1.z; As[lc + 7][lr] = a1.w;
        Bs[lc + 0][lr] = b0.x; Bs[lc + 1][lr] = b0.y; Bs[lc + 2][lr] = b0.z; Bs[lc + 3][lr] = b0.w;
        Bs[lc + 4][lr] = b1.x; Bs[lc + 5][lr] = b1.y; Bs[lc + 6][lr] = b1.z; Bs[lc + 7][lr] = b1.w;
        __syncthreads();
#pragma unroll
        for (int k = 0; k < BK; k++) {
            float4 av = *(const float4*)(&As[k][tm]);
            float4 bv = *(const float4*)(&Bs[k][tn]);
            float a[4] = {av.x, av.y, av.z, av.w};
            float b[4] = {bv.x, bv.y, bv.z, bv.w};
#pragma unroll
            for (int i = 0; i < 4; i++)
#pragma unroll
                for (int j = 0; j < 4; j++) acc[i][j] += a[i] * b[j];
        }
    }
#pragma unroll
    for (int i = 0; i < 4; i++)
#pragma unroll
        for (int j = 0; j < 4; j++)
            atomicAdd(&g_gates[(size_t)(bm + tm + i) * 1024 + bn + tn + j], acc[i][j]);
}

// ---------------- e-pass: e[rank] = dot(feat[perm], h[g]); segment max ----------------
// 8 warps per block, each warp 4 consecutive ranks; dir flips traversal for L2 reuse
__global__ void k_epass(const float* __restrict__ feat, int N, int nblocks, int dir) {
    int b = dir ? (nblocks - 1 - (int)blockIdx.x) : (int)blockIdx.x;
    int warp = threadIdx.x >> 5, lane = threadIdx.x & 31;
    int base = b * 32 + warp * 4;
#pragma unroll
    for (int j = 0; j < 4; j++) {
        int rank = base + j;
        if (rank >= N) break;
        int n = g_perm[rank];
        int g = g_grank[rank];
        const float4* fr = (const float4*)(feat + (size_t)n * D);
        const float4* qr = (const float4*)(g_xbuf + (size_t)g * 512);
        float s = 0.0f;
#pragma unroll
        for (int k = 0; k < 2; k++) {
            float4 f4 = fr[k * 32 + lane];
            float4 q4 = qr[k * 32 + lane];
            s += f4.x * q4.x + f4.y * q4.y + f4.z * q4.z + f4.w * q4.w;
        }
#pragma unroll
        for (int o = 16; o; o >>= 1) s += __shfl_xor_sync(0xffffffffu, s, o);
        if (lane == 0) {
            g_e[rank] = s;
            atomicMax(&g_gmaxe[g], fenc(s));
        }
    }
}

// ---------------- sum of exp(e - max), with warp-uniform aggregation ----------------
__global__ void k_sumexp(int N) {
    int i = blockIdx.x * blockDim.x + threadIdx.x;
    bool valid = (i < N);
    int g = valid ? g_grank[i] : -1;
    float ex = 0.0f;
    if (valid) {
        float m = fdec(g_gmaxe[g]);
        ex = expf(g_e[i] - m);
        g_e[i] = ex;
    }
    unsigned full = 0xffffffffu;
    int g0 = __shfl_sync(full, g, 0);
    bool uni = __all_sync(full, g == g0);
    if (uni && g0 >= 0) {
        float s = ex;
#pragma unroll
        for (int o = 16; o; o >>= 1) s += __shfl_xor_sync(full, s, o);
        if ((threadIdx.x & 31) == 0) atomicAdd(&g_gsum[g0], s);
    } else if (valid) {
        atomicAdd(&g_gsum[g], ex);
    }
}

// ---------------- r-pass: r[g] += a * feat, register accumulation per dim ----------------
#define RCHUNK 256
__global__ void k_rpass(const float* __restrict__ feat, int N, int nchunks, int dir) {
    __shared__ float se[RCHUNK];
    __shared__ int   sn[RCHUNK];
    __shared__ int   sg[RCHUNK];
    int c = dir ? (nchunks - 1 - (int)blockIdx.x) : (int)blockIdx.x;
    int base = c * RCHUNK;
    int cnt = min(RCHUNK, N - base);
    int t = threadIdx.x;   // 256 = D dims
    if (t < cnt) {
        se[t] = g_e[base + t];
        sn[t] = g_perm[base + t];
        sg[t] = g_grank[base + t];
    }
    __syncthreads();
    float acc = 0.0f;
    int cur = sg[0];
    for (int j = 0; j < cnt; j++) {
        int gj = sg[j];
        if (gj != cur) {
            float inv = 1.0f / (g_gsum[cur] + 1e-16f);
            atomicAdd(&g_xbuf[(size_t)cur * 512 + D + t], acc * inv);
            acc = 0.0f;
            cur = gj;
        }
        acc += se[j] * feat[(size_t)sn[j] * D + t];
    }
    float inv = 1.0f / (g_gsum[cur] + 1e-16f);
    atomicAdd(&g_xbuf[(size_t)cur * 512 + D + t], acc * inv);
}

// ---------------- copy result out ----------------
__global__ void k_copyout(float* __restrict__ out) {
    int i = blockIdx.x * blockDim.x + threadIdx.x;
    if (i < G * 512) out[i] = g_xbuf[i];
}

// ---------------- host launcher ----------------
extern "C" void kernel_launch(void* const* d_in, const int* in_sizes, int n_in,
                              void* d_out, int out_size) {
    const float* feat  = (const float*)d_in[0];
    const int*   bidx  = (const int*)d_in[1];
    const float* W_ih  = (const float*)d_in[2];
    const float* W_hh  = (const float*)d_in[3];
    const float* b_ih  = (const float*)d_in[4];
    const float* b_hh  = (const float*)d_in[5];
    float* out = (float*)d_out;

    int N = in_sizes[0] / D;

    k_prep<<<(1024 * 512 + 255) / 256, 256>>>(W_ih, W_hh, b_ih, b_hh);
    k_hist<<<512, 256>>>(bidx, N);
    k_scan<<<1, 512>>>();
    k_scatter<<<(N + 255) / 256, 256>>>(bidx, N);

    int eblocks = (N + 31) / 32;
    int rchunks = (N + RCHUNK - 1) / RCHUNK;

    for (int step = 0; step < 3; step++) {
        if (step == 0) {
            k_cell0<<<(G * D + 255) / 256, 256>>>();
        } else {
            dim3 grid(1024 / BN, 512 / BM, 2);   // split-K = 2
            k_gemm<<<grid, 256>>>();
            k_cellk<<<(G * D + 255) / 256, 256>>>();
        }
        k_epass<<<eblocks, 256>>>(feat, N, eblocks, /*dir=*/0);
        k_sumexp<<<(N + 255) / 256, 256>>>(N);
        k_rpass<<<rchunks, 256>>>(feat, N, rchunks, /*dir=*/1);
    }

    k_copyout<<<(G * 512 + 255) / 256, 256>>>(out);
}

// round 2
// speedup vs baseline: 1.9916x; 1.9916x over previous
#include <cuda_runtime.h>
#include <cuda_bf16.h>
#include <math.h>

#define G 512
#define D 256
#define MAXN 204800

// ---------------- device scratch ----------------
__device__ float    g_Wc[1024 * 512];     // combined weight [4D x 2D]
__device__ float    g_biasc[1024];        // b_ih + b_hh
__device__ int      g_counts[G];
__device__ int      g_cursor[G];
__device__ int      g_perm[MAXN];         // node id sorted by graph
__device__ int      g_grank[MAXN];        // graph id per rank
__device__ float    g_e[MAXN];            // e, then exp(e-max)
__device__ float    g_xbuf[G * 512];      // q_star layout: [h | r] per graph
__device__ float    g_cbuf[G * D];        // LSTM cell state
__device__ float    g_gates[G * 1024];    // GEMM accumulator (zeroed between uses)
__device__ unsigned g_gmaxe[G];           // order-encoded float max
__device__ float    g_gsum[G];

// order-preserving float<->uint encoding for atomicMax
__device__ __forceinline__ unsigned fenc(float f) {
    unsigned u = __float_as_uint(f);
    return (u & 0x80000000u) ? ~u : (u | 0x80000000u);
}
__device__ __forceinline__ float fdec(unsigned u) {
    return (u & 0x80000000u) ? __uint_as_float(u ^ 0x80000000u)
                             : __uint_as_float(~u);
}
#define ENC_NEG_INF 0x007FFFFFu   // fenc(-inf)

__device__ __forceinline__ float sigf(float x) { return 1.0f / (1.0f + expf(-x)); }

// ---------------- prep: combined weights, bias, zero counts ----------------
__global__ void k_prep(const float* __restrict__ W_ih, const float* __restrict__ W_hh,
                       const float* __restrict__ b_ih, const float* __restrict__ b_hh) {
    int i = blockIdx.x * blockDim.x + threadIdx.x;
    if (i < 1024 * 512) {
        int j = i >> 9, k = i & 511;
        float w = W_ih[i];
        if (k < D) w += W_hh[j * D + k];
        g_Wc[i] = w;
    }
    if (i < 1024) g_biasc[i] = b_ih[i] + b_hh[i];
    if (i < G) g_counts[i] = 0;
}

// ---------------- counting sort of nodes by graph ----------------
__global__ void k_hist(const int* __restrict__ bidx, int N) {
    __shared__ int sh[G];
    for (int i = threadIdx.x; i < G; i += blockDim.x) sh[i] = 0;
    __syncthreads();
    for (int i = blockIdx.x * blockDim.x + threadIdx.x; i < N; i += gridDim.x * blockDim.x)
        atomicAdd(&sh[bidx[i]], 1);
    __syncthreads();
    for (int i = threadIdx.x; i < G; i += blockDim.x)
        if (sh[i]) atomicAdd(&g_counts[i], sh[i]);
}

__global__ void k_scan() {   // one block, 512 threads
    __shared__ int s[G];
    int t = threadIdx.x;
    s[t] = g_counts[t];
    __syncthreads();
    for (int o = 1; o < G; o <<= 1) {
        int v = 0;
        if (t >= o) v = s[t - o];
        __syncthreads();
        if (t >= o) s[t] += v;
        __syncthreads();
    }
    g_cursor[t] = s[t] - g_counts[t];   // exclusive prefix
}

// Block-aggregated scatter: one global atomic per (block, present-graph),
// then smem-cursor placement. 2048 elements per block.
#define SCHUNK 2048
__global__ void __launch_bounds__(256) k_scatter(const int* __restrict__ bidx, int N) {
    __shared__ int hist[G];
    int t = threadIdx.x;
    int b0 = blockIdx.x * SCHUNK;
    for (int i = t; i < G; i += 256) hist[i] = 0;
    __syncthreads();
#pragma unroll
    for (int k = 0; k < SCHUNK / 256; k++) {
        int i = b0 + k * 256 + t;
        if (i < N) atomicAdd(&hist[bidx[i]], 1);
    }
    __syncthreads();
    for (int gidx = t; gidx < G; gidx += 256) {
        int c = hist[gidx];
        if (c > 0) hist[gidx] = atomicAdd(&g_cursor[gidx], c);
    }
    __syncthreads();
#pragma unroll
    for (int k = 0; k < SCHUNK / 256; k++) {
        int i = b0 + k * 256 + t;
        if (i < N) {
            int g = bidx[i];
            int p = atomicAdd(&hist[g], 1);
            g_perm[p] = i;
            g_grank[p] = g;
        }
    }
}

// ---------------- step-1 LSTM: all state zero -> gates = bias ----------------
__global__ void k_cell0() {
    int idx = blockIdx.x * blockDim.x + threadIdx.x;   // < G*D
    int g = idx >> 8, d = idx & 255;
    float i_ = sigf(g_biasc[d]);
    float gg = tanhf(g_biasc[512 + d]);
    float o_ = sigf(g_biasc[768 + d]);
    float c = i_ * gg;
    float h = o_ * tanhf(c);
    g_cbuf[idx] = c;
    g_xbuf[g * 512 + d] = h;
    g_xbuf[g * 512 + D + d] = 0.0f;
    if (idx < G) { g_gmaxe[idx] = ENC_NEG_INF; g_gsum[idx] = 0.0f; }
#pragma unroll
    for (int k = 0; k < 4; k++) g_gates[idx * 4 + k] = 0.0f;   // zero full gates buffer
}

// ---------------- steps 2,3 LSTM cell (gates precomputed by GEMM) ----------------
__global__ void k_cellk() {
    int idx = blockIdx.x * blockDim.x + threadIdx.x;   // < G*D
    int g = idx >> 8, d = idx & 255;
    int base = g * 1024;
    float gi = g_gates[base + d]       + g_biasc[d];
    float gf = g_gates[base + 256 + d] + g_biasc[256 + d];
    float gg = g_gates[base + 512 + d] + g_biasc[512 + d];
    float go = g_gates[base + 768 + d] + g_biasc[768 + d];
    float i_ = sigf(gi), f_ = sigf(gf), gt = tanhf(gg), o_ = sigf(go);
    float c = f_ * g_cbuf[idx] + i_ * gt;
    float h = o_ * tanhf(c);
    g_cbuf[idx] = c;
    g_xbuf[g * 512 + d] = h;
    g_xbuf[g * 512 + D + d] = 0.0f;      // zero r accumulator
    // re-zero gates for the next GEMM's atomic accumulation
    g_gates[base + d] = 0.0f; g_gates[base + 256 + d] = 0.0f;
    g_gates[base + 512 + d] = 0.0f; g_gates[base + 768 + d] = 0.0f;
    if (idx < G) { g_gmaxe[idx] = ENC_NEG_INF; g_gsum[idx] = 0.0f; }
}

// ---------------- GEMM: gates += xbuf[512x512] @ Wc^T[512x1024], split-K=2 ----------------
#define BM 64
#define BN 64
#define BK 32
__global__ void __launch_bounds__(256) k_gemm() {
    __shared__ float As[BK][BM + 4];
    __shared__ float Bs[BK][BN + 4];
    int tid = threadIdx.x;
    int bm = blockIdx.y * BM;
    int bn = blockIdx.x * BN;
    int k0 = blockIdx.z * 256;
    int lr = tid >> 2;            // 0..63 tile row for loading
    int lc = (tid & 3) * 8;       // k offset 0,8,16,24
    int tm = (tid >> 4) * 4;      // compute micro-tile
    int tn = (tid & 15) * 4;
    float acc[4][4] = {};
    for (int kt = 0; kt < 256; kt += BK) {
        const float4* ap = (const float4*)(g_xbuf + (size_t)(bm + lr) * 512 + k0 + kt + lc);
        float4 a0 = ap[0], a1 = ap[1];
        const float4* bp = (const float4*)(g_Wc + (size_t)(bn + lr) * 512 + k0 + kt + lc);
        float4 b0 = bp[0], b1 = bp[1];
        __syncthreads();
        As[lc + 0][lr] = a0.x; As[lc + 1][lr] = a0.y; As[lc + 2][lr] = a0.z; As[lc + 3][lr] = a0.w;
        As[lc + 4][lr] = a1.x; As[lc + 5][lr] = a1.y; As[lc + 6][lr] = a1.z; As[lc + 7][lr] = a1.w;
        Bs[lc + 0][lr] = b0.x; Bs[lc + 1][lr] = b0.y; Bs[lc + 2][lr] = b0.z; Bs[lc + 3][lr] = b0.w;
        Bs[lc + 4][lr] = b1.x; Bs[lc + 5][lr] = b1.y; Bs[lc + 6][lr] = b1.z; Bs[lc + 7][lr] = b1.w;
        __syncthreads();
#pragma unroll
        for (int k = 0; k < BK; k++) {
            float4 av = *(const float4*)(&As[k][tm]);
            float4 bv = *(const float4*)(&Bs[k][tn]);
            float a[4] = {av.x, av.y, av.z, av.w};
            float b[4] = {bv.x, bv.y, bv.z, bv.w};
#pragma unroll
            for (int i = 0; i < 4; i++)
#pragma unroll
                for (int j = 0; j < 4; j++) acc[i][j] += a[i] * b[j];
        }
    }
#pragma unroll
    for (int i = 0; i < 4; i++)
#pragma unroll
        for (int j = 0; j < 4; j++)
            atomicAdd(&g_gates[(size_t)(bm + tm + i) * 1024 + bn + tn + j], acc[i][j]);
}

// ---------------- e-pass: e[rank] = dot(feat[perm], h[g]); segment max ----------------
// 8 warps per block, each warp 4 consecutive ranks, fully unrolled + predicated.
__global__ void __launch_bounds__(256) k_epass(const float* __restrict__ feat, int N) {
    int warp = threadIdx.x >> 5, lane = threadIdx.x & 31;
    int base = (blockIdx.x * 8 + warp) * 4;
    if (base >= N) return;
    int   nn[4], gg[4];
    float s[4];
#pragma unroll
    for (int j = 0; j < 4; j++) {
        int rank = min(base + j, N - 1);
        nn[j] = g_perm[rank];
        gg[j] = g_grank[rank];
    }
#pragma unroll
    for (int j = 0; j < 4; j++) {
        const float4* fr = (const float4*)(feat + (size_t)nn[j] * D);
        const float4* qr = (const float4*)(g_xbuf + (size_t)gg[j] * 512);
        float4 f0 = fr[lane],      q0 = qr[lane];
        float4 f1 = fr[32 + lane], q1 = qr[32 + lane];
        s[j] = f0.x * q0.x + f0.y * q0.y + f0.z * q0.z + f0.w * q0.w
             + f1.x * q1.x + f1.y * q1.y + f1.z * q1.z + f1.w * q1.w;
    }
#pragma unroll
    for (int j = 0; j < 4; j++) {
#pragma unroll
        for (int o = 16; o; o >>= 1) s[j] += __shfl_xor_sync(0xffffffffu, s[j], o);
        if (lane == 0 && base + j < N) {
            g_e[base + j] = s[j];
            atomicMax(&g_gmaxe[gg[j]], fenc(s[j]));
        }
    }
}

// ---------------- sum of exp(e - max), with warp-uniform aggregation ----------------
__global__ void k_sumexp(int N) {
    int i = blockIdx.x * blockDim.x + threadIdx.x;
    bool valid = (i < N);
    int g = valid ? g_grank[i] : -1;
    float ex = 0.0f;
    if (valid) {
        float m = fdec(g_gmaxe[g]);
        ex = expf(g_e[i] - m);
        g_e[i] = ex;
    }
    unsigned full = 0xffffffffu;
    int g0 = __shfl_sync(full, g, 0);
    bool uni = __all_sync(full, g == g0);
    if (uni && g0 >= 0) {
        float s = ex;
#pragma unroll
        for (int o = 16; o; o >>= 1) s += __shfl_xor_sync(full, s, o);
        if ((threadIdx.x & 31) == 0) atomicAdd(&g_gsum[g0], s);
    } else if (valid) {
        atomicAdd(&g_gsum[g], ex);
    }
}

// ---------------- r-pass: warp-per-run register accumulation ----------------
// Each warp owns 32 contiguous ranks; each lane accumulates 8 dims (2 x float4).
// Flush (scaled by 1/sum) via atomicAdd only at segment boundaries.
__device__ __forceinline__ void r_flush(int g, float4 a0, float4 a1, int lane) {
    float inv = 1.0f / (g_gsum[g] + 1e-16f);
    float* base = g_xbuf + (size_t)g * 512 + D;
    atomicAdd(base + lane * 4 + 0,   a0.x * inv);
    atomicAdd(base + lane * 4 + 1,   a0.y * inv);
    atomicAdd(base + lane * 4 + 2,   a0.z * inv);
    atomicAdd(base + lane * 4 + 3,   a0.w * inv);
    atomicAdd(base + 128 + lane * 4 + 0, a1.x * inv);
    atomicAdd(base + 128 + lane * 4 + 1, a1.y * inv);
    atomicAdd(base + 128 + lane * 4 + 2, a1.z * inv);
    atomicAdd(base + 128 + lane * 4 + 3, a1.w * inv);
}

#define RPB 256   // ranks per block (8 warps x 32 ranks)
__global__ void __launch_bounds__(256) k_rpass(const float* __restrict__ feat,
                                               int N, int nblocks, int dir) {
    int b = dir ? (nblocks - 1 - (int)blockIdx.x) : (int)blockIdx.x;
    int warp = threadIdx.x >> 5, lane = threadIdx.x & 31;
    int start = b * RPB + warp * 32;
    int end = min(start + 32, N);
    if (start >= end) return;
    float4 a0 = make_float4(0.f, 0.f, 0.f, 0.f);
    float4 a1 = make_float4(0.f, 0.f, 0.f, 0.f);
    int cur = g_grank[start];
#pragma unroll 4
    for (int r = start; r < end; r++) {
        int n   = g_perm[r];
        int grp = g_grank[r];
        float w = g_e[r];
        const float4* fr = (const float4*)(feat + (size_t)n * D);
        float4 f0 = fr[lane];
        float4 f1 = fr[32 + lane];
        if (grp != cur) {           // rare: segment boundary
            r_flush(cur, a0, a1, lane);
            a0 = make_float4(0.f, 0.f, 0.f, 0.f);
            a1 = make_float4(0.f, 0.f, 0.f, 0.f);
            cur = grp;
        }
        a0.x += w * f0.x; a0.y += w * f0.y; a0.z += w * f0.z; a0.w += w * f0.w;
        a1.x += w * f1.x; a1.y += w * f1.y; a1.z += w * f1.z; a1.w += w * f1.w;
    }
    r_flush(cur, a0, a1, lane);
}

// ---------------- copy result out ----------------
__global__ void k_copyout(float* __restrict__ out) {
    int i = blockIdx.x * blockDim.x + threadIdx.x;
    if (i < G * 512) out[i] = g_xbuf[i];
}

// ---------------- host launcher ----------------
extern "C" void kernel_launch(void* const* d_in, const int* in_sizes, int n_in,
                              void* d_out, int out_size) {
    const float* feat  = (const float*)d_in[0];
    const int*   bidx  = (const int*)d_in[1];
    const float* W_ih  = (const float*)d_in[2];
    const float* W_hh  = (const float*)d_in[3];
    const float* b_ih  = (const float*)d_in[4];
    const float* b_hh  = (const float*)d_in[5];
    float* out = (float*)d_out;

    int N = in_sizes[0] / D;

    k_prep<<<(1024 * 512 + 255) / 256, 256>>>(W_ih, W_hh, b_ih, b_hh);
    k_hist<<<512, 256>>>(bidx, N);
    k_scan<<<1, 512>>>();
    k_scatter<<<(N + SCHUNK - 1) / SCHUNK, 256>>>(bidx, N);

    int eblocks = (N + 31) / 32;
    int rblocks = (N + RPB - 1) / RPB;

    for (int step = 0; step < 3; step++) {
        if (step == 0) {
            k_cell0<<<(G * D + 255) / 256, 256>>>();
        } else {
            dim3 grid(1024 / BN, 512 / BM, 2);   // split-K = 2
            k_gemm<<<grid, 256>>>();
            k_cellk<<<(G * D + 255) / 256, 256>>>();
        }
        k_epass<<<eblocks, 256>>>(feat, N);
        k_sumexp<<<(N + 255) / 256, 256>>>(N);
        k_rpass<<<rblocks, 256>>>(feat, N, rblocks, /*dir=*/1);
    }

    k_copyout<<<(G * 512 + 255) / 256, 256>>>(out);
}

// round 4
// speedup vs baseline: 2.1089x; 1.0589x over previous
#include <cuda_runtime.h>
#include <cuda_fp16.h>
#include <math.h>

#define G 512
#define D 256
#define MAXN 204800

// ---------------- device scratch ----------------
__device__ float    g_Wc[1024 * 512];       // combined weight [4D x 2D]
__device__ float    g_biasc[1024];          // b_ih + b_hh
__device__ int      g_counts[G];
__device__ int      g_cursor[G];
__device__ int      g_perm[MAXN];           // node id sorted by graph
__device__ int      g_grank[MAXN];          // graph id per rank
__device__ float    g_e[MAXN];              // raw logits e per rank
__device__ float    g_xbuf[G * 512];        // q_star layout: [h | r] per graph
__device__ float    g_cbuf[G * D];          // LSTM cell state
__device__ float    g_gates[G * 1024];      // GEMM accumulator (zeroed between uses)
__device__ unsigned g_gmaxe[G];             // order-encoded float max
__device__ float    g_gsum[G];              // sum of exp (unnormalized)
__device__ __half2  g_feat16[MAXN * (D/2)]; // fp16 features, permuted to rank order (102 MB)

// bit reinterpret helpers
__device__ __forceinline__ unsigned h2_as_u32(__half2 h) {
    union { __half2 h; unsigned u; } cvt; cvt.h = h; return cvt.u;
}
__device__ __forceinline__ __half2 u32_as_h2(unsigned u) {
    union { unsigned u; __half2 h; } cvt; cvt.u = u; return cvt.h;
}

// order-preserving float<->uint encoding for atomicMax
__device__ __forceinline__ unsigned fenc(float f) {
    unsigned u = __float_as_uint(f);
    return (u & 0x80000000u) ? ~u : (u | 0x80000000u);
}
__device__ __forceinline__ float fdec(unsigned u) {
    return (u & 0x80000000u) ? __uint_as_float(u ^ 0x80000000u)
                             : __uint_as_float(~u);
}
#define ENC_NEG_INF 0x007FFFFFu   // fenc(-inf)

__device__ __forceinline__ float sigf(float x) { return 1.0f / (1.0f + expf(-x)); }

// ---------------- prep: combined weights, bias, zero counts ----------------
__global__ void k_prep(const float* __restrict__ W_ih, const float* __restrict__ W_hh,
                       const float* __restrict__ b_ih, const float* __restrict__ b_hh) {
    int i = blockIdx.x * blockDim.x + threadIdx.x;
    if (i < 1024 * 512) {
        int j = i >> 9, k = i & 511;
        float w = W_ih[i];
        if (k < D) w += W_hh[j * D + k];
        g_Wc[i] = w;
    }
    if (i < 1024) g_biasc[i] = b_ih[i] + b_hh[i];
    if (i < G) g_counts[i] = 0;
}

// ---------------- counting sort of nodes by graph ----------------
__global__ void k_hist(const int* __restrict__ bidx, int N) {
    __shared__ int sh[G];
    for (int i = threadIdx.x; i < G; i += blockDim.x) sh[i] = 0;
    __syncthreads();
    for (int i = blockIdx.x * blockDim.x + threadIdx.x; i < N; i += gridDim.x * blockDim.x)
        atomicAdd(&sh[bidx[i]], 1);
    __syncthreads();
    for (int i = threadIdx.x; i < G; i += blockDim.x)
        if (sh[i]) atomicAdd(&g_counts[i], sh[i]);
}

__global__ void k_scan() {   // one block, 512 threads
    __shared__ int s[G];
    int t = threadIdx.x;
    s[t] = g_counts[t];
    __syncthreads();
    for (int o = 1; o < G; o <<= 1) {
        int v = 0;
        if (t >= o) v = s[t - o];
        __syncthreads();
        if (t >= o) s[t] += v;
        __syncthreads();
    }
    g_cursor[t] = s[t] - g_counts[t];   // exclusive prefix
}

// Block-aggregated scatter: one global atomic per (block, present-graph).
#define SCHUNK 1024
__global__ void __launch_bounds__(256) k_scatter(const int* __restrict__ bidx, int N) {
    __shared__ int hist[G];
    int t = threadIdx.x;
    int b0 = blockIdx.x * SCHUNK;
    for (int i = t; i < G; i += 256) hist[i] = 0;
    __syncthreads();
#pragma unroll
    for (int k = 0; k < SCHUNK / 256; k++) {
        int i = b0 + k * 256 + t;
        if (i < N) atomicAdd(&hist[bidx[i]], 1);
    }
    __syncthreads();
    for (int gidx = t; gidx < G; gidx += 256) {
        int c = hist[gidx];
        if (c > 0) hist[gidx] = atomicAdd(&g_cursor[gidx], c);
    }
    __syncthreads();
#pragma unroll
    for (int k = 0; k < SCHUNK / 256; k++) {
        int i = b0 + k * 256 + t;
        if (i < N) {
            int g = bidx[i];
            int p = atomicAdd(&hist[g], 1);
            g_perm[p] = i;
            g_grank[p] = g;
        }
    }
}

// ---------------- fp16 feature conversion, permuted to rank order ----------------
// warp per row: gather fp32 row feat[perm[rank]], store fp16 row at [rank].
__global__ void __launch_bounds__(256) k_convert(const float* __restrict__ feat, int N) {
    int warp = threadIdx.x >> 5, lane = threadIdx.x & 31;
    int rank = blockIdx.x * 8 + warp;
    if (rank >= N) return;
    int n = g_perm[rank];
    const float4* src = (const float4*)(feat + (size_t)n * D);
    float4 a = src[lane * 2], b = src[lane * 2 + 1];
    uint4 out;
    out.x = h2_as_u32(__floats2half2_rn(a.x, a.y));
    out.y = h2_as_u32(__floats2half2_rn(a.z, a.w));
    out.z = h2_as_u32(__floats2half2_rn(b.x, b.y));
    out.w = h2_as_u32(__floats2half2_rn(b.z, b.w));
    ((uint4*)(g_feat16 + (size_t)rank * (D / 2)))[lane] = out;
}

// ---------------- step-1 LSTM: all state zero -> gates = bias ----------------
__global__ void k_cell0() {
    int idx = blockIdx.x * blockDim.x + threadIdx.x;   // < G*D
    int g = idx >> 8, d = idx & 255;
    float i_ = sigf(g_biasc[d]);
    float gg = tanhf(g_biasc[512 + d]);
    float o_ = sigf(g_biasc[768 + d]);
    float c = i_ * gg;
    float h = o_ * tanhf(c);
    g_cbuf[idx] = c;
    g_xbuf[g * 512 + d] = h;
    g_xbuf[g * 512 + D + d] = 0.0f;
    if (idx < G) { g_gmaxe[idx] = ENC_NEG_INF; g_gsum[idx] = 0.0f; }
#pragma unroll
    for (int k = 0; k < 4; k++) g_gates[idx * 4 + k] = 0.0f;   // zero full gates buffer
}

// ---------------- steps 2,3 LSTM cell (gates precomputed by GEMM) ----------------
__global__ void k_cellk() {
    int idx = blockIdx.x * blockDim.x + threadIdx.x;   // < G*D
    int g = idx >> 8, d = idx & 255;
    int base = g * 1024;
    float gi = g_gates[base + d]       + g_biasc[d];
    float gf = g_gates[base + 256 + d] + g_biasc[256 + d];
    float gg = g_gates[base + 512 + d] + g_biasc[512 + d];
    float go = g_gates[base + 768 + d] + g_biasc[768 + d];
    float i_ = sigf(gi), f_ = sigf(gf), gt = tanhf(gg), o_ = sigf(go);
    float c = f_ * g_cbuf[idx] + i_ * gt;
    float h = o_ * tanhf(c);
    g_cbuf[idx] = c;
    g_xbuf[g * 512 + d] = h;
    g_xbuf[g * 512 + D + d] = 0.0f;      // zero r accumulator
    // re-zero gates for the next GEMM's atomic accumulation
    g_gates[base + d] = 0.0f; g_gates[base + 256 + d] = 0.0f;
    g_gates[base + 512 + d] = 0.0f; g_gates[base + 768 + d] = 0.0f;
    if (idx < G) { g_gmaxe[idx] = ENC_NEG_INF; g_gsum[idx] = 0.0f; }
}

// ---------------- GEMM: gates += xbuf[512x512] @ Wc^T[512x1024], split-K=2 ----------------
#define BM 64
#define BN 64
#define BK 32
__global__ void __launch_bounds__(256) k_gemm() {
    __shared__ float As[BK][BM + 4];
    __shared__ float Bs[BK][BN + 4];
    int tid = threadIdx.x;
    int bm = blockIdx.y * BM;
    int bn = blockIdx.x * BN;
    int k0 = blockIdx.z * 256;
    int lr = tid >> 2;            // 0..63 tile row for loading
    int lc = (tid & 3) * 8;       // k offset 0,8,16,24
    int tm = (tid >> 4) * 4;      // compute micro-tile
    int tn = (tid & 15) * 4;
    float acc[4][4] = {};
    for (int kt = 0; kt < 256; kt += BK) {
        const float4* ap = (const float4*)(g_xbuf + (size_t)(bm + lr) * 512 + k0 + kt + lc);
        float4 a0 = ap[0], a1 = ap[1];
        const float4* bp = (const float4*)(g_Wc + (size_t)(bn + lr) * 512 + k0 + kt + lc);
        float4 b0 = bp[0], b1 = bp[1];
        __syncthreads();
        As[lc + 0][lr] = a0.x; As[lc + 1][lr] = a0.y; As[lc + 2][lr] = a0.z; As[lc + 3][lr] = a0.w;
        As[lc + 4][lr] = a1.x; As[lc + 5][lr] = a1.y; As[lc + 6][lr] = a1.z; As[lc + 7][lr] = a1.w;
        Bs[lc + 0][lr] = b0.x; Bs[lc + 1][lr] = b0.y; Bs[lc + 2][lr] = b0.z; Bs[lc + 3][lr] = b0.w;
        Bs[lc + 4][lr] = b1.x; Bs[lc + 5][lr] = b1.y; Bs[lc + 6][lr] = b1.z; Bs[lc + 7][lr] = b1.w;
        __syncthreads();
#pragma unroll
        for (int k = 0; k < BK; k++) {
            float4 av = *(const float4*)(&As[k][tm]);
            float4 bv = *(const float4*)(&Bs[k][tn]);
            float a[4] = {av.x, av.y, av.z, av.w};
            float b[4] = {bv.x, bv.y, bv.z, bv.w};
#pragma unroll
            for (int i = 0; i < 4; i++)
#pragma unroll
                for (int j = 0; j < 4; j++) acc[i][j] += a[i] * b[j];
        }
    }
#pragma unroll
    for (int i = 0; i < 4; i++)
#pragma unroll
        for (int j = 0; j < 4; j++)
            atomicAdd(&g_gates[(size_t)(bm + tm + i) * 1024 + bn + tn + j], acc[i][j]);
}

// ---------------- e-pass: e[rank] = dot(feat16[rank], h[g]); segment max ----------------
// 8 warps per block, warp handles 4 consecutive ranks (2KB contiguous fp16).
__global__ void __launch_bounds__(256) k_epass(int N) {
    int warp = threadIdx.x >> 5, lane = threadIdx.x & 31;
    int base = (blockIdx.x * 8 + warp) * 4;
    if (base >= N) return;
    int gg[4];
    float s[4];
#pragma unroll
    for (int j = 0; j < 4; j++) gg[j] = g_grank[min(base + j, N - 1)];
#pragma unroll
    for (int j = 0; j < 4; j++) {
        int rank = min(base + j, N - 1);
        uint4 fv = ((const uint4*)(g_feat16 + (size_t)rank * (D / 2)))[lane];
        const float4* qr = (const float4*)(g_xbuf + (size_t)gg[j] * 512);
        float4 q0 = qr[lane * 2], q1 = qr[lane * 2 + 1];
        float2 f0 = __half22float2(u32_as_h2(fv.x));
        float2 f1 = __half22float2(u32_as_h2(fv.y));
        float2 f2 = __half22float2(u32_as_h2(fv.z));
        float2 f3 = __half22float2(u32_as_h2(fv.w));
        s[j] = f0.x * q0.x + f0.y * q0.y + f1.x * q0.z + f1.y * q0.w
             + f2.x * q1.x + f2.y * q1.y + f3.x * q1.z + f3.y * q1.w;
    }
#pragma unroll
    for (int j = 0; j < 4; j++) {
#pragma unroll
        for (int o = 16; o; o >>= 1) s[j] += __shfl_xor_sync(0xffffffffu, s[j], o);
        if (lane == 0 && base + j < N) {
            g_e[base + j] = s[j];
            atomicMax(&g_gmaxe[gg[j]], fenc(s[j]));
        }
    }
}

// ---------------- r-pass (fused exp + weighted sum + sum-of-exp) ----------------
// Warp owns 32 contiguous ranks; lane accumulates 8 dims. Unnormalized sums;
// atomic flush only at segment boundaries.
__device__ __forceinline__ void r_flush(int g, const float* acc, float wsum, int lane) {
    float* base = g_xbuf + (size_t)g * 512 + D + lane * 8;
#pragma unroll
    for (int k = 0; k < 8; k++) atomicAdd(base + k, acc[k]);
    if (lane == 0) atomicAdd(&g_gsum[g], wsum);
}

#define RPB 256   // ranks per block (8 warps x 32 ranks)
__global__ void __launch_bounds__(256) k_rpass(int N, int nblocks) {
    int b = nblocks - 1 - (int)blockIdx.x;   // reverse traversal for L2 reuse
    int warp = threadIdx.x >> 5, lane = threadIdx.x & 31;
    int start = b * RPB + warp * 32;
    int end = min(start + 32, N);
    if (start >= end) return;
    float acc[8] = {};
    float wsum = 0.0f;
    int cur = g_grank[start];
    float curmax = fdec(g_gmaxe[cur]);
#pragma unroll 4
    for (int r = start; r < end; r++) {
        int grp = g_grank[r];
        float e  = g_e[r];
        uint4 fv = ((const uint4*)(g_feat16 + (size_t)r * (D / 2)))[lane];
        if (grp != cur) {           // rare: segment boundary
            r_flush(cur, acc, wsum, lane);
#pragma unroll
            for (int k = 0; k < 8; k++) acc[k] = 0.0f;
            wsum = 0.0f;
            cur = grp;
            curmax = fdec(g_gmaxe[cur]);
        }
        float w = expf(e - curmax);
        wsum += w;
        float2 f0 = __half22float2(u32_as_h2(fv.x));
        float2 f1 = __half22float2(u32_as_h2(fv.y));
        float2 f2 = __half22float2(u32_as_h2(fv.z));
        float2 f3 = __half22float2(u32_as_h2(fv.w));
        acc[0] += w * f0.x; acc[1] += w * f0.y;
        acc[2] += w * f1.x; acc[3] += w * f1.y;
        acc[4] += w * f2.x; acc[5] += w * f2.y;
        acc[6] += w * f3.x; acc[7] += w * f3.y;
    }
    r_flush(cur, acc, wsum, lane);
}

// ---------------- normalize r by sum of exp ----------------
__global__ void k_norm() {
    int idx = blockIdx.x * blockDim.x + threadIdx.x;   // < G*D
    int g = idx >> 8, d = idx & 255;
    float inv = 1.0f / (g_gsum[g] + 1e-16f);
    g_xbuf[(size_t)g * 512 + D + d] *= inv;
}

// ---------------- copy result out ----------------
__global__ void k_copyout(float* __restrict__ out) {
    int i = blockIdx.x * blockDim.x + threadIdx.x;
    if (i < G * 512) out[i] = g_xbuf[i];
}

// ---------------- host launcher ----------------
extern "C" void kernel_launch(void* const* d_in, const int* in_sizes, int n_in,
                              void* d_out, int out_size) {
    const float* feat  = (const float*)d_in[0];
    const int*   bidx  = (const int*)d_in[1];
    const float* W_ih  = (const float*)d_in[2];
    const float* W_hh  = (const float*)d_in[3];
    const float* b_ih  = (const float*)d_in[4];
    const float* b_hh  = (const float*)d_in[5];
    float* out = (float*)d_out;

    int N = in_sizes[0] / D;

    k_prep<<<(1024 * 512 + 255) / 256, 256>>>(W_ih, W_hh, b_ih, b_hh);
    k_hist<<<512, 256>>>(bidx, N);
    k_scan<<<1, 512>>>();
    k_scatter<<<(N + SCHUNK - 1) / SCHUNK, 256>>>(bidx, N);
    k_convert<<<(N + 7) / 8, 256>>>(feat, N);

    int eblocks = (N + 31) / 32;
    int rblocks = (N + RPB - 1) / RPB;

    for (int step = 0; step < 3; step++) {
        if (step == 0) {
            k_cell0<<<(G * D + 255) / 256, 256>>>();
        } else {
            dim3 grid(1024 / BN, 512 / BM, 2);   // split-K = 2
            k_gemm<<<grid, 256>>>();
            k_cellk<<<(G * D + 255) / 256, 256>>>();
        }
        k_epass<<<eblocks, 256>>>(N);
        k_rpass<<<rblocks, 256>>>(N, rblocks);
        k_norm<<<(G * D + 255) / 256, 256>>>();
    }

    k_copyout<<<(G * 512 + 255) / 256, 256>>>(out);
}

// round 5
// speedup vs baseline: 3.3886x; 1.6068x over previous
#include <cuda_runtime.h>
#include <cuda_fp16.h>
#include <math.h>

#define G 512
#define D 256
#define MAXN 204800
#define ATTN_MAXGRID 592   // 148 SMs x 4 blocks

// ---------------- device scratch ----------------
__device__ float    g_Wc[1024 * 512];       // combined weight [4D x 2D]
__device__ float    g_biasc[1024];          // b_ih + b_hh
__device__ int      g_counts[G];            // zero-init; k_scan resets after use
__device__ int      g_cursor[G];
__device__ int      g_perm[MAXN];           // node id sorted by graph
__device__ int      g_grank[MAXN];          // graph id per rank
__device__ float    g_e[MAXN];              // raw logits e per rank
__device__ float    g_xbuf[G * 512];        // q_star layout: [h | r(unnormalized)]
__device__ float    g_cbuf[G * D];          // LSTM cell state
__device__ float    g_gates[G * 1024];      // GEMM accumulator
__device__ unsigned g_gmaxe[G];             // order-encoded float max
__device__ float    g_gsum[G];              // sum of exp (unnormalized)
__device__ __half2  g_feat16[MAXN * (D/2)]; // fp16 features, rank order (102 MB)
__device__ int          g_bar_count;
__device__ volatile int g_bar_gen;

// bit reinterpret helpers
__device__ __forceinline__ unsigned h2_as_u32(__half2 h) {
    union { __half2 h; unsigned u; } c; c.h = h; return c.u;
}
__device__ __forceinline__ __half2 u32_as_h2(unsigned u) {
    union { unsigned u; __half2 h; } c; c.u = u; return c.h;
}

// order-preserving float<->uint encoding for atomicMax
__device__ __forceinline__ unsigned fenc(float f) {
    unsigned u = __float_as_uint(f);
    return (u & 0x80000000u) ? ~u : (u | 0x80000000u);
}
__device__ __forceinline__ float fdec(unsigned u) {
    return (u & 0x80000000u) ? __uint_as_float(u ^ 0x80000000u)
                             : __uint_as_float(~u);
}
#define ENC_NEG_INF 0x007FFFFFu

__device__ __forceinline__ float sigf(float x) { return 1.0f / (1.0f + expf(-x)); }

// ---------------- software grid barrier (grid must be fully resident) ----------
__device__ __forceinline__ void grid_barrier() {
    __syncthreads();
    if (threadIdx.x == 0) {
        __threadfence();
        int gen = g_bar_gen;
        asm volatile("" ::: "memory");
        if (atomicAdd(&g_bar_count, 1) == (int)gridDim.x - 1) {
            g_bar_count = 0;
            __threadfence();
            atomicAdd((int*)&g_bar_gen, 1);
        } else {
            while (g_bar_gen == gen) __nanosleep(64);
        }
        __threadfence();
    }
    __syncthreads();
}

// ---------------- combined preamble: Wc/bias prep | histogram | LSTM step-1 ----
__global__ void __launch_bounds__(256) k_pre(const float* __restrict__ W_ih,
                                             const float* __restrict__ W_hh,
                                             const float* __restrict__ b_ih,
                                             const float* __restrict__ b_hh,
                                             const int* __restrict__ bidx, int N) {
    int b = blockIdx.x;
    if (b < 2048) {                       // weight combine + bias
        int i = b * 256 + threadIdx.x;
        int j = i >> 9, k = i & 511;
        float w = W_ih[i];
        if (k < D) w += W_hh[j * D + k];
        g_Wc[i] = w;
        if (i < 1024) g_biasc[i] = b_ih[i] + b_hh[i];
    } else if (b < 2560) {                // histogram (512 blocks, strided)
        __shared__ int sh[G];
        for (int i = threadIdx.x; i < G; i += 256) sh[i] = 0;
        __syncthreads();
        for (int i = (b - 2048) * 256 + threadIdx.x; i < N; i += 512 * 256)
            atomicAdd(&sh[bidx[i]], 1);
        __syncthreads();
        for (int i = threadIdx.x; i < G; i += 256)
            if (sh[i]) atomicAdd(&g_counts[i], sh[i]);
    } else {                              // LSTM step 1 (zero state): gates = bias
        int idx = (b - 2560) * 256 + threadIdx.x;   // < G*D
        int g = idx >> 8, d = idx & 255;
        float bi = b_ih[d]       + b_hh[d];
        float bg = b_ih[512 + d] + b_hh[512 + d];
        float bo = b_ih[768 + d] + b_hh[768 + d];
        float i_ = sigf(bi), gt = tanhf(bg), o_ = sigf(bo);
        float c = i_ * gt;
        float h = o_ * tanhf(c);
        g_cbuf[idx] = c;
        g_xbuf[g * 512 + d] = h;
        g_xbuf[g * 512 + D + d] = 0.0f;
        if (idx < G) { g_gmaxe[idx] = ENC_NEG_INF; g_gsum[idx] = 0.0f; }
#pragma unroll
        for (int k2 = 0; k2 < 4; k2++) g_gates[idx * 4 + k2] = 0.0f;
    }
}

// ---------------- prefix scan (resets g_counts for next replay) ----------------
__global__ void k_scan() {
    __shared__ int s[G];
    int t = threadIdx.x;
    s[t] = g_counts[t];
    __syncthreads();
    for (int o = 1; o < G; o <<= 1) {
        int v = 0;
        if (t >= o) v = s[t - o];
        __syncthreads();
        if (t >= o) s[t] += v;
        __syncthreads();
    }
    g_cursor[t] = s[t] - g_counts[t];
    g_counts[t] = 0;
}

// ---------------- block-aggregated scatter ----------------
#define SCHUNK 1024
__global__ void __launch_bounds__(256) k_scatter(const int* __restrict__ bidx, int N) {
    __shared__ int hist[G];
    int t = threadIdx.x;
    int b0 = blockIdx.x * SCHUNK;
    for (int i = t; i < G; i += 256) hist[i] = 0;
    __syncthreads();
#pragma unroll
    for (int k = 0; k < SCHUNK / 256; k++) {
        int i = b0 + k * 256 + t;
        if (i < N) atomicAdd(&hist[bidx[i]], 1);
    }
    __syncthreads();
    for (int gidx = t; gidx < G; gidx += 256) {
        int c = hist[gidx];
        if (c > 0) hist[gidx] = atomicAdd(&g_cursor[gidx], c);
    }
    __syncthreads();
#pragma unroll
    for (int k = 0; k < SCHUNK / 256; k++) {
        int i = b0 + k * 256 + t;
        if (i < N) {
            int g = bidx[i];
            int p = atomicAdd(&hist[g], 1);
            g_perm[p] = i;
            g_grank[p] = g;
        }
    }
}

// ---------------- LSTM cell for steps 2,3 ----------------
__global__ void k_cellk() {
    int idx = blockIdx.x * blockDim.x + threadIdx.x;   // < G*D
    int g = idx >> 8, d = idx & 255;
    int base = g * 1024;
    float gi = g_gates[base + d]       + g_biasc[d];
    float gf = g_gates[base + 256 + d] + g_biasc[256 + d];
    float gg = g_gates[base + 512 + d] + g_biasc[512 + d];
    float go = g_gates[base + 768 + d] + g_biasc[768 + d];
    float i_ = sigf(gi), f_ = sigf(gf), gt = tanhf(gg), o_ = sigf(go);
    float c = f_ * g_cbuf[idx] + i_ * gt;
    float h = o_ * tanhf(c);
    g_cbuf[idx] = c;
    g_xbuf[g * 512 + d] = h;
    g_xbuf[g * 512 + D + d] = 0.0f;
    g_gates[base + d] = 0.0f; g_gates[base + 256 + d] = 0.0f;
    g_gates[base + 512 + d] = 0.0f; g_gates[base + 768 + d] = 0.0f;
    if (idx < G) { g_gmaxe[idx] = ENC_NEG_INF; g_gsum[idx] = 0.0f; }
}

// ---------------- GEMM: gates += q_star @ Wc^T, split-K=2, norm folded ---------
#define BM 64
#define BN 64
#define BK 32
__global__ void __launch_bounds__(256) k_gemm() {
    __shared__ float As[BK][BM + 4];
    __shared__ float Bs[BK][BN + 4];
    int tid = threadIdx.x;
    int bm = blockIdx.y * BM;
    int bn = blockIdx.x * BN;
    int k0 = blockIdx.z * 256;
    int lr = tid >> 2;
    int lc = (tid & 3) * 8;
    int tm = (tid >> 4) * 4;
    int tn = (tid & 15) * 4;
    // z==1 covers K columns [256,512) = r columns -> scale by 1/sum(exp)
    float inv = 1.0f;
    if (blockIdx.z == 1) inv = 1.0f / (g_gsum[bm + lr] + 1e-16f);
    float acc[4][4] = {};
    for (int kt = 0; kt < 256; kt += BK) {
        const float4* ap = (const float4*)(g_xbuf + (size_t)(bm + lr) * 512 + k0 + kt + lc);
        float4 a0 = ap[0], a1 = ap[1];
        a0.x *= inv; a0.y *= inv; a0.z *= inv; a0.w *= inv;
        a1.x *= inv; a1.y *= inv; a1.z *= inv; a1.w *= inv;
        const float4* bp = (const float4*)(g_Wc + (size_t)(bn + lr) * 512 + k0 + kt + lc);
        float4 b0 = bp[0], b1 = bp[1];
        __syncthreads();
        As[lc + 0][lr] = a0.x; As[lc + 1][lr] = a0.y; As[lc + 2][lr] = a0.z; As[lc + 3][lr] = a0.w;
        As[lc + 4][lr] = a1.x; As[lc + 5][lr] = a1.y; As[lc + 6][lr] = a1.z; As[lc + 7][lr] = a1.w;
        Bs[lc + 0][lr] = b0.x; Bs[lc + 1][lr] = b0.y; Bs[lc + 2][lr] = b0.z; Bs[lc + 3][lr] = b0.w;
        Bs[lc + 4][lr] = b1.x; Bs[lc + 5][lr] = b1.y; Bs[lc + 6][lr] = b1.z; Bs[lc + 7][lr] = b1.w;
        __syncthreads();
#pragma unroll
        for (int k = 0; k < BK; k++) {
            float4 av = *(const float4*)(&As[k][tm]);
            float4 bv = *(const float4*)(&Bs[k][tn]);
            float a[4] = {av.x, av.y, av.z, av.w};
            float b[4] = {bv.x, bv.y, bv.z, bv.w};
#pragma unroll
            for (int i = 0; i < 4; i++)
#pragma unroll
                for (int j = 0; j < 4; j++) acc[i][j] += a[i] * b[j];
        }
    }
#pragma unroll
    for (int i = 0; i < 4; i++)
#pragma unroll
        for (int j = 0; j < 4; j++)
            atomicAdd(&g_gates[(size_t)(bm + tm + i) * 1024 + bn + tn + j], acc[i][j]);
}

// ---------------- phase 2 helper: flush accumulated r + wsum ----------------
__device__ __forceinline__ void r_flush(int g, const float* acc, float wsum, int lane) {
    float* base = g_xbuf + (size_t)g * 512 + D + lane * 8;
#pragma unroll
    for (int k = 0; k < 8; k++) atomicAdd(base + k, acc[k]);
    if (lane == 0) atomicAdd(&g_gsum[g], wsum);
}

__device__ __forceinline__ void rpass_range(int ws, int we, int lane) {
    if (ws >= we) return;
    float acc[8] = {};
    float wsum = 0.0f;
    int cur = g_grank[ws];
    float curmax = fdec(g_gmaxe[cur]);
#pragma unroll 4
    for (int r = ws; r < we; r++) {
        int grp  = g_grank[r];
        float e  = g_e[r];
        uint4 fv = ((const uint4*)(g_feat16 + (size_t)r * (D / 2)))[lane];
        if (grp != cur) {
            r_flush(cur, acc, wsum, lane);
#pragma unroll
            for (int k = 0; k < 8; k++) acc[k] = 0.0f;
            wsum = 0.0f;
            cur = grp;
            curmax = fdec(g_gmaxe[cur]);
        }
        float w = expf(e - curmax);
        wsum += w;
        float2 f0 = __half22float2(u32_as_h2(fv.x));
        float2 f1 = __half22float2(u32_as_h2(fv.y));
        float2 f2 = __half22float2(u32_as_h2(fv.z));
        float2 f3 = __half22float2(u32_as_h2(fv.w));
        acc[0] += w * f0.x; acc[1] += w * f0.y;
        acc[2] += w * f1.x; acc[3] += w * f1.y;
        acc[4] += w * f2.x; acc[5] += w * f2.y;
        acc[6] += w * f3.x; acc[7] += w * f3.y;
    }
    r_flush(cur, acc, wsum, lane);
}

// ---------------- fused attention, step 1: convert + logits | barrier | rpass ---
__global__ void __launch_bounds__(256, 4) k_attn0(const float* __restrict__ feat, int N) {
    int warp = threadIdx.x >> 5, lane = threadIdx.x & 31;
    int per = (N + gridDim.x - 1) / gridDim.x;
    int bs = blockIdx.x * per;
    int be = min(bs + per, N);
    int sub = (per + 7) >> 3;
    int ws = min(bs + warp * sub, be);
    int we = min(ws + sub, be);

    if (ws < we) {
        int curg = -1; float curm = 0.0f;
        for (int r0 = ws; r0 < we; r0 += 4) {
            int cnt = min(4, we - r0);
            float s4[4]; int g4[4];
#pragma unroll
            for (int j = 0; j < 4; j++) {
                int rk = r0 + ((j < cnt) ? j : (cnt - 1));
                g4[j] = g_grank[rk];
                int n = g_perm[rk];
                const float4* fr = (const float4*)(feat + (size_t)n * D);
                float4 a = fr[lane * 2], b = fr[lane * 2 + 1];
                const float4* qr = (const float4*)(g_xbuf + (size_t)g4[j] * 512);
                float4 q0 = qr[lane * 2], q1 = qr[lane * 2 + 1];
                s4[j] = a.x * q0.x + a.y * q0.y + a.z * q0.z + a.w * q0.w
                      + b.x * q1.x + b.y * q1.y + b.z * q1.z + b.w * q1.w;
                if (j < cnt) {   // emit fp16 cache row
                    uint4 o16;
                    o16.x = h2_as_u32(__floats2half2_rn(a.x, a.y));
                    o16.y = h2_as_u32(__floats2half2_rn(a.z, a.w));
                    o16.z = h2_as_u32(__floats2half2_rn(b.x, b.y));
                    o16.w = h2_as_u32(__floats2half2_rn(b.z, b.w));
                    ((uint4*)(g_feat16 + (size_t)rk * (D / 2)))[lane] = o16;
                }
            }
#pragma unroll
            for (int j = 0; j < 4; j++)
#pragma unroll
                for (int o = 16; o; o >>= 1) s4[j] += __shfl_xor_sync(0xffffffffu, s4[j], o);
            for (int j = 0; j < cnt; j++) {
                if (lane == 0) g_e[r0 + j] = s4[j];
                if (g4[j] != curg) {
                    if (curg >= 0 && lane == 0) atomicMax(&g_gmaxe[curg], fenc(curm));
                    curg = g4[j]; curm = s4[j];
                } else curm = fmaxf(curm, s4[j]);
            }
        }
        if (curg >= 0 && lane == 0) atomicMax(&g_gmaxe[curg], fenc(curm));
    }
    grid_barrier();
    rpass_range(ws, we, lane);
}

// ---------------- fused attention, steps 2-3 (fp16 path) ----------------
__global__ void __launch_bounds__(256, 4) k_attn(int N) {
    int warp = threadIdx.x >> 5, lane = threadIdx.x & 31;
    int per = (N + gridDim.x - 1) / gridDim.x;
    int bs = blockIdx.x * per;
    int be = min(bs + per, N);
    int sub = (per + 7) >> 3;
    int ws = min(bs + warp * sub, be);
    int we = min(ws + sub, be);

    if (ws < we) {
        int curg = -1; float curm = 0.0f;
        for (int r0 = ws; r0 < we; r0 += 4) {
            int cnt = min(4, we - r0);
            float s4[4]; int g4[4];
#pragma unroll
            for (int j = 0; j < 4; j++) {
                int rk = r0 + ((j < cnt) ? j : (cnt - 1));
                g4[j] = g_grank[rk];
                uint4 fv = ((const uint4*)(g_feat16 + (size_t)rk * (D / 2)))[lane];
                const float4* qr = (const float4*)(g_xbuf + (size_t)g4[j] * 512);
                float4 q0 = qr[lane * 2], q1 = qr[lane * 2 + 1];
                float2 f0 = __half22float2(u32_as_h2(fv.x));
                float2 f1 = __half22float2(u32_as_h2(fv.y));
                float2 f2 = __half22float2(u32_as_h2(fv.z));
                float2 f3 = __half22float2(u32_as_h2(fv.w));
                s4[j] = f0.x * q0.x + f0.y * q0.y + f1.x * q0.z + f1.y * q0.w
                      + f2.x * q1.x + f2.y * q1.y + f3.x * q1.z + f3.y * q1.w;
            }
#pragma unroll
            for (int j = 0; j < 4; j++)
#pragma unroll
                for (int o = 16; o; o >>= 1) s4[j] += __shfl_xor_sync(0xffffffffu, s4[j], o);
            for (int j = 0; j < cnt; j++) {
                if (lane == 0) g_e[r0 + j] = s4[j];
                if (g4[j] != curg) {
                    if (curg >= 0 && lane == 0) atomicMax(&g_gmaxe[curg], fenc(curm));
                    curg = g4[j]; curm = s4[j];
                } else curm = fmaxf(curm, s4[j]);
            }
        }
        if (curg >= 0 && lane == 0) atomicMax(&g_gmaxe[curg], fenc(curm));
    }
    grid_barrier();
    rpass_range(ws, we, lane);
}

// ---------------- copy result out (normalize r here) ----------------
__global__ void k_copyout(float* __restrict__ out) {
    int i = blockIdx.x * blockDim.x + threadIdx.x;
    if (i < G * 512) {
        int g = i >> 9, d = i & 511;
        float v = g_xbuf[i];
        if (d >= D) v *= 1.0f / (g_gsum[g] + 1e-16f);
        out[i] = v;
    }
}

// ---------------- host launcher ----------------
extern "C" void kernel_launch(void* const* d_in, const int* in_sizes, int n_in,
                              void* d_out, int out_size) {
    const float* feat  = (const float*)d_in[0];
    const int*   bidx  = (const int*)d_in[1];
    const float* W_ih  = (const float*)d_in[2];
    const float* W_hh  = (const float*)d_in[3];
    const float* b_ih  = (const float*)d_in[4];
    const float* b_hh  = (const float*)d_in[5];
    float* out = (float*)d_out;

    int N = in_sizes[0] / D;

    // residency-safe persistent grid for barrier kernels
    int sms = 148, occ0 = 1, occ1 = 1;
    cudaDeviceGetAttribute(&sms, cudaDevAttrMultiProcessorCount, 0);
    cudaOccupancyMaxActiveBlocksPerMultiprocessor(&occ0, k_attn0, 256, 0);
    cudaOccupancyMaxActiveBlocksPerMultiprocessor(&occ1, k_attn, 256, 0);
    int occ = occ0 < occ1 ? occ0 : occ1;
    if (occ < 1) occ = 1;
    int agrid = sms * occ;
    if (agrid > ATTN_MAXGRID) agrid = ATTN_MAXGRID;

    k_pre<<<3072, 256>>>(W_ih, W_hh, b_ih, b_hh, bidx, N);
    k_scan<<<1, 512>>>();
    k_scatter<<<(N + SCHUNK - 1) / SCHUNK, 256>>>(bidx, N);

    k_attn0<<<agrid, 256>>>(feat, N);
    for (int step = 1; step < 3; step++) {
        dim3 grid(1024 / BN, 512 / BM, 2);
        k_gemm<<<grid, 256>>>();
        k_cellk<<<(G * D + 255) / 256, 256>>>();
        k_attn<<<agrid, 256>>>(N);
    }
    k_copyout<<<(G * 512 + 255) / 256, 256>>>(out);
}

// round 6
// speedup vs baseline: 3.6520x; 1.0777x over previous
#include <cuda_runtime.h>
#include <cuda_fp16.h>
#include <math.h>

#define G 512
#define D 256
#define MAXN 204800
#define ATTN_MAXGRID 592   // 148 SMs x 4 blocks

// ---------------- device scratch ----------------
__device__ float    g_Wc[1024 * 512];       // combined weight [4D x 2D]
__device__ float    g_biasc[1024];          // b_ih + b_hh
__device__ int      g_counts[G];            // zero-init; k_scan resets after use
__device__ int      g_cursor[G];
__device__ int      g_perm[MAXN];           // node id sorted by graph
__device__ int      g_grank[MAXN];          // graph id per rank
__device__ float    g_xbuf[G * 512];        // q_star layout: [h | r(unnormalized)]
__device__ float    g_cbuf[G * D];          // LSTM cell state
__device__ float    g_gates[G * 1024];      // GEMM accumulator
__device__ unsigned g_gmaxe[G];             // order-encoded float max
__device__ float    g_gsum[G];              // sum of exp (unnormalized)
__device__ __half2  g_feat16[MAXN * (D/2)]; // fp16 features, rank order (102 MB)
__device__ int          g_bar_count;
__device__ volatile int g_bar_gen;

// bit reinterpret helpers
__device__ __forceinline__ unsigned h2_as_u32(__half2 h) {
    union { __half2 h; unsigned u; } c; c.h = h; return c.u;
}
__device__ __forceinline__ __half2 u32_as_h2(unsigned u) {
    union { unsigned u; __half2 h; } c; c.u = u; return c.h;
}

// order-preserving float<->uint encoding for atomicMax
__device__ __forceinline__ unsigned fenc(float f) {
    unsigned u = __float_as_uint(f);
    return (u & 0x80000000u) ? ~u : (u | 0x80000000u);
}
__device__ __forceinline__ float fdec(unsigned u) {
    return (u & 0x80000000u) ? __uint_as_float(u ^ 0x80000000u)
                             : __uint_as_float(~u);
}
#define ENC_NEG_INF 0x007FFFFFu

__device__ __forceinline__ float sigf(float x) { return 1.0f / (1.0f + expf(-x)); }

// ---------------- software grid barrier (grid must be fully resident) ----------
__device__ __forceinline__ void grid_barrier() {
    __syncthreads();
    if (threadIdx.x == 0) {
        __threadfence();
        int gen = g_bar_gen;
        asm volatile("" ::: "memory");
        if (atomicAdd(&g_bar_count, 1) == (int)gridDim.x - 1) {
            g_bar_count = 0;
            __threadfence();
            atomicAdd((int*)&g_bar_gen, 1);
        } else {
            while (g_bar_gen == gen) __nanosleep(64);
        }
        __threadfence();
    }
    __syncthreads();
}

// ---------------- combined preamble: Wc/bias prep | histogram | LSTM step-1 ----
__global__ void __launch_bounds__(256) k_pre(const float* __restrict__ W_ih,
                                             const float* __restrict__ W_hh,
                                             const float* __restrict__ b_ih,
                                             const float* __restrict__ b_hh,
                                             const int* __restrict__ bidx, int N) {
    int b = blockIdx.x;
    if (b < 2048) {                       // weight combine + bias
        int i = b * 256 + threadIdx.x;
        int j = i >> 9, k = i & 511;
        float w = W_ih[i];
        if (k < D) w += W_hh[j * D + k];
        g_Wc[i] = w;
        if (i < 1024) g_biasc[i] = b_ih[i] + b_hh[i];
    } else if (b < 2560) {                // histogram (512 blocks, strided)
        __shared__ int sh[G];
        for (int i = threadIdx.x; i < G; i += 256) sh[i] = 0;
        __syncthreads();
        for (int i = (b - 2048) * 256 + threadIdx.x; i < N; i += 512 * 256)
            atomicAdd(&sh[bidx[i]], 1);
        __syncthreads();
        for (int i = threadIdx.x; i < G; i += 256)
            if (sh[i]) atomicAdd(&g_counts[i], sh[i]);
    } else {                              // LSTM step 1 (zero state): gates = bias
        int idx = (b - 2560) * 256 + threadIdx.x;   // < G*D
        int g = idx >> 8, d = idx & 255;
        float bi = b_ih[d]       + b_hh[d];
        float bg = b_ih[512 + d] + b_hh[512 + d];
        float bo = b_ih[768 + d] + b_hh[768 + d];
        float i_ = sigf(bi), gt = tanhf(bg), o_ = sigf(bo);
        float c = i_ * gt;
        float h = o_ * tanhf(c);
        g_cbuf[idx] = c;
        g_xbuf[g * 512 + d] = h;
        g_xbuf[g * 512 + D + d] = 0.0f;
        if (idx < G) { g_gmaxe[idx] = ENC_NEG_INF; g_gsum[idx] = 0.0f; }
#pragma unroll
        for (int k2 = 0; k2 < 4; k2++) g_gates[idx * 4 + k2] = 0.0f;
    }
}

// ---------------- prefix scan (resets g_counts for next replay) ----------------
__global__ void k_scan() {
    __shared__ int s[G];
    int t = threadIdx.x;
    s[t] = g_counts[t];
    __syncthreads();
    for (int o = 1; o < G; o <<= 1) {
        int v = 0;
        if (t >= o) v = s[t - o];
        __syncthreads();
        if (t >= o) s[t] += v;
        __syncthreads();
    }
    g_cursor[t] = s[t] - g_counts[t];
    g_counts[t] = 0;
}

// ---------------- block-aggregated scatter ----------------
#define SCHUNK 1024
__global__ void __launch_bounds__(256) k_scatter(const int* __restrict__ bidx, int N) {
    __shared__ int hist[G];
    int t = threadIdx.x;
    int b0 = blockIdx.x * SCHUNK;
    for (int i = t; i < G; i += 256) hist[i] = 0;
    __syncthreads();
#pragma unroll
    for (int k = 0; k < SCHUNK / 256; k++) {
        int i = b0 + k * 256 + t;
        if (i < N) atomicAdd(&hist[bidx[i]], 1);
    }
    __syncthreads();
    for (int gidx = t; gidx < G; gidx += 256) {
        int c = hist[gidx];
        if (c > 0) hist[gidx] = atomicAdd(&g_cursor[gidx], c);
    }
    __syncthreads();
#pragma unroll
    for (int k = 0; k < SCHUNK / 256; k++) {
        int i = b0 + k * 256 + t;
        if (i < N) {
            int g = bidx[i];
            int p = atomicAdd(&hist[g], 1);
            g_perm[p] = i;
            g_grank[p] = g;
        }
    }
}

// ---------------- LSTM cell for steps 2,3 ----------------
__global__ void k_cellk() {
    int idx = blockIdx.x * blockDim.x + threadIdx.x;   // < G*D
    int g = idx >> 8, d = idx & 255;
    int base = g * 1024;
    float gi = g_gates[base + d]       + g_biasc[d];
    float gf = g_gates[base + 256 + d] + g_biasc[256 + d];
    float gg = g_gates[base + 512 + d] + g_biasc[512 + d];
    float go = g_gates[base + 768 + d] + g_biasc[768 + d];
    float i_ = sigf(gi), f_ = sigf(gf), gt = tanhf(gg), o_ = sigf(go);
    float c = f_ * g_cbuf[idx] + i_ * gt;
    float h = o_ * tanhf(c);
    g_cbuf[idx] = c;
    g_xbuf[g * 512 + d] = h;
    g_xbuf[g * 512 + D + d] = 0.0f;
    g_gates[base + d] = 0.0f; g_gates[base + 256 + d] = 0.0f;
    g_gates[base + 512 + d] = 0.0f; g_gates[base + 768 + d] = 0.0f;
    if (idx < G) { g_gmaxe[idx] = ENC_NEG_INF; g_gsum[idx] = 0.0f; }
}

// ---------------- GEMM: gates += q_star @ Wc^T, split-K=4, norm folded ---------
#define BM 64
#define BN 64
#define BK 32
__global__ void __launch_bounds__(256) k_gemm() {
    __shared__ float As[BK][BM + 4];
    __shared__ float Bs[BK][BN + 4];
    int tid = threadIdx.x;
    int bm = blockIdx.y * BM;
    int bn = blockIdx.x * BN;
    int k0 = blockIdx.z * 128;
    int lr = tid >> 2;
    int lc = (tid & 3) * 8;
    int tm = (tid >> 4) * 4;
    int tn = (tid & 15) * 4;
    // z>=2 covers K columns [256,512) = r columns -> scale by 1/sum(exp)
    float inv = 1.0f;
    if (blockIdx.z >= 2) inv = 1.0f / (g_gsum[bm + lr] + 1e-16f);
    float acc[4][4] = {};
    for (int kt = 0; kt < 128; kt += BK) {
        const float4* ap = (const float4*)(g_xbuf + (size_t)(bm + lr) * 512 + k0 + kt + lc);
        float4 a0 = ap[0], a1 = ap[1];
        a0.x *= inv; a0.y *= inv; a0.z *= inv; a0.w *= inv;
        a1.x *= inv; a1.y *= inv; a1.z *= inv; a1.w *= inv;
        const float4* bp = (const float4*)(g_Wc + (size_t)(bn + lr) * 512 + k0 + kt + lc);
        float4 b0 = bp[0], b1 = bp[1];
        __syncthreads();
        As[lc + 0][lr] = a0.x; As[lc + 1][lr] = a0.y; As[lc + 2][lr] = a0.z; As[lc + 3][lr] = a0.w;
        As[lc + 4][lr] = a1.x; As[lc + 5][lr] = a1.y; As[lc + 6][lr] = a1.z; As[lc + 7][lr] = a1.w;
        Bs[lc + 0][lr] = b0.x; Bs[lc + 1][lr] = b0.y; Bs[lc + 2][lr] = b0.z; Bs[lc + 3][lr] = b0.w;
        Bs[lc + 4][lr] = b1.x; Bs[lc + 5][lr] = b1.y; Bs[lc + 6][lr] = b1.z; Bs[lc + 7][lr] = b1.w;
        __syncthreads();
#pragma unroll
        for (int k = 0; k < BK; k++) {
            float4 av = *(const float4*)(&As[k][tm]);
            float4 bv = *(const float4*)(&Bs[k][tn]);
            float a[4] = {av.x, av.y, av.z, av.w};
            float b[4] = {bv.x, bv.y, bv.z, bv.w};
#pragma unroll
            for (int i = 0; i < 4; i++)
#pragma unroll
                for (int j = 0; j < 4; j++) acc[i][j] += a[i] * b[j];
        }
    }
#pragma unroll
    for (int i = 0; i < 4; i++)
#pragma unroll
        for (int j = 0; j < 4; j++)
            atomicAdd(&g_gates[(size_t)(bm + tm + i) * 1024 + bn + tn + j], acc[i][j]);
}

// ---------------- online softmax helpers ----------------
__device__ __forceinline__ void load_q(int g, int lane, float* q) {
    const float4* qr = (const float4*)(g_xbuf + (size_t)g * 512);
    float4 q0 = qr[lane * 2], q1 = qr[lane * 2 + 1];
    q[0] = q0.x; q[1] = q0.y; q[2] = q0.z; q[3] = q0.w;
    q[4] = q1.x; q[5] = q1.y; q[6] = q1.z; q[7] = q1.w;
}

// global flush: rescale partial (m,s,acc) to the global max, then atomicAdd
__device__ __forceinline__ void o_flush_global(int g, float m, float s,
                                               const float* acc, int lane) {
    float M = fdec(g_gmaxe[g]);
    float sc = __expf(m - M);
    float* base = g_xbuf + (size_t)g * 512 + D + lane * 8;
#pragma unroll
    for (int k = 0; k < 8; k++) atomicAdd(base + k, acc[k] * sc);
    if (lane == 0) atomicAdd(&g_gsum[g], s * sc);
}

// local flush: sole-owner segment; (acc,s) pair is internally consistent, and
// r/gsum is invariant under the common scale, so no global-max rescale needed.
__device__ __forceinline__ void o_flush_local(int g, float s, const float* acc, int lane) {
    float* base = g_xbuf + (size_t)g * 512 + D + lane * 8;
#pragma unroll
    for (int k = 0; k < 8; k++) atomicAdd(base + k, acc[k]);
    if (lane == 0) atomicAdd(&g_gsum[g], s);
}

// online update for one rank: e is warp-uniform, f[8] per lane
__device__ __forceinline__ void o_update(float e, const float* f,
                                         float& m, float& s, float* acc) {
    if (e > m) {
        float sc = __expf(m - e);
        s *= sc;
#pragma unroll
        for (int k = 0; k < 8; k++) acc[k] *= sc;
        m = e;
    }
    float w = __expf(e - m);
    s += w;
#pragma unroll
    for (int k = 0; k < 8; k++) acc[k] += w * f[k];
}

// ---------------- fused attention step 1: fp32 gather + fp16 emit, online -----
__global__ void __launch_bounds__(256, 4) k_attn0(const float* __restrict__ feat, int N) {
    int warp = threadIdx.x >> 5, lane = threadIdx.x & 31;
    int per = (N + gridDim.x - 1) / gridDim.x;
    int bs = blockIdx.x * per;
    int be = min(bs + per, N);
    int sub = (per + 7) >> 3;
    int ws = min(bs + warp * sub, be);
    int we = min(ws + sub, be);

    int curg = -1, pg = -1;
    bool started_inside = false;
    float m = -1e30f, s = 0.0f, pm = 0.0f, ps = 0.0f;
    float acc[8] = {}, pacc[8];
    float q[8];

    if (ws < we) {
        curg = g_grank[ws];
        load_q(curg, lane, q);
        for (int r = ws; r < we; r++) {
            int grp = g_grank[r];
            int n = g_perm[r];
            const float4* fr = (const float4*)(feat + (size_t)n * D);
            float4 a = fr[lane * 2], b = fr[lane * 2 + 1];
            // emit fp16 cache row
            uint4 o16;
            o16.x = h2_as_u32(__floats2half2_rn(a.x, a.y));
            o16.y = h2_as_u32(__floats2half2_rn(a.z, a.w));
            o16.z = h2_as_u32(__floats2half2_rn(b.x, b.y));
            o16.w = h2_as_u32(__floats2half2_rn(b.z, b.w));
            ((uint4*)(g_feat16 + (size_t)r * (D / 2)))[lane] = o16;
            float f[8] = {a.x, a.y, a.z, a.w, b.x, b.y, b.z, b.w};
            if (grp != curg) {                 // segment boundary
                if (started_inside) {          // complete interior segment
                    o_flush_local(curg, s, acc, lane);
                } else {
                    pg = curg; pm = m; ps = s;
#pragma unroll
                    for (int k = 0; k < 8; k++) pacc[k] = acc[k];
                }
                started_inside = true;
                m = -1e30f; s = 0.0f;
#pragma unroll
                for (int k = 0; k < 8; k++) acc[k] = 0.0f;
                curg = grp;
                load_q(curg, lane, q);
            }
            float e = f[0]*q[0] + f[1]*q[1] + f[2]*q[2] + f[3]*q[3]
                    + f[4]*q[4] + f[5]*q[5] + f[6]*q[6] + f[7]*q[7];
#pragma unroll
            for (int o = 16; o; o >>= 1) e += __shfl_xor_sync(0xffffffffu, e, o);
            o_update(e, f, m, s, acc);
        }
        if (lane == 0) {
            atomicMax(&g_gmaxe[curg], fenc(m));
            if (pg >= 0) atomicMax(&g_gmaxe[pg], fenc(pm));
        }
    }
    grid_barrier();
    if (ws < we) {
        o_flush_global(curg, m, s, acc, lane);
        if (pg >= 0) o_flush_global(pg, pm, ps, pacc, lane);
    }
}

// ---------------- fused attention steps 2-3: fp16 path, online ----------------
__global__ void __launch_bounds__(256, 4) k_attn(int N) {
    int warp = threadIdx.x >> 5, lane = threadIdx.x & 31;
    int per = (N + gridDim.x - 1) / gridDim.x;
    int bs = blockIdx.x * per;
    int be = min(bs + per, N);
    int sub = (per + 7) >> 3;
    int ws = min(bs + warp * sub, be);
    int we = min(ws + sub, be);

    int curg = -1, pg = -1;
    bool started_inside = false;
    float m = -1e30f, s = 0.0f, pm = 0.0f, ps = 0.0f;
    float acc[8] = {}, pacc[8];
    float q[8];

    if (ws < we) {
        curg = g_grank[ws];
        load_q(curg, lane, q);
        for (int r = ws; r < we; r++) {
            int grp = g_grank[r];
            uint4 fv = ((const uint4*)(g_feat16 + (size_t)r * (D / 2)))[lane];
            float2 f0 = __half22float2(u32_as_h2(fv.x));
            float2 f1 = __half22float2(u32_as_h2(fv.y));
            float2 f2 = __half22float2(u32_as_h2(fv.z));
            float2 f3 = __half22float2(u32_as_h2(fv.w));
            float f[8] = {f0.x, f0.y, f1.x, f1.y, f2.x, f2.y, f3.x, f3.y};
            if (grp != curg) {
                if (started_inside) {
                    o_flush_local(curg, s, acc, lane);
                } else {
                    pg = curg; pm = m; ps = s;
#pragma unroll
                    for (int k = 0; k < 8; k++) pacc[k] = acc[k];
                }
                started_inside = true;
                m = -1e30f; s = 0.0f;
#pragma unroll
                for (int k = 0; k < 8; k++) acc[k] = 0.0f;
                curg = grp;
                load_q(curg, lane, q);
            }
            float e = f[0]*q[0] + f[1]*q[1] + f[2]*q[2] + f[3]*q[3]
                    + f[4]*q[4] + f[5]*q[5] + f[6]*q[6] + f[7]*q[7];
#pragma unroll
            for (int o = 16; o; o >>= 1) e += __shfl_xor_sync(0xffffffffu, e, o);
            o_update(e, f, m, s, acc);
        }
        if (lane == 0) {
            atomicMax(&g_gmaxe[curg], fenc(m));
            if (pg >= 0) atomicMax(&g_gmaxe[pg], fenc(pm));
        }
    }
    grid_barrier();
    if (ws < we) {
        o_flush_global(curg, m, s, acc, lane);
        if (pg >= 0) o_flush_global(pg, pm, ps, pacc, lane);
    }
}

// ---------------- copy result out (normalize r here) ----------------
__global__ void k_copyout(float* __restrict__ out) {
    int i = blockIdx.x * blockDim.x + threadIdx.x;
    if (i < G * 512) {
        int g = i >> 9, d = i & 511;
        float v = g_xbuf[i];
        if (d >= D) v *= 1.0f / (g_gsum[g] + 1e-16f);
        out[i] = v;
    }
}

// ---------------- host launcher ----------------
extern "C" void kernel_launch(void* const* d_in, const int* in_sizes, int n_in,
                              void* d_out, int out_size) {
    const float* feat  = (const float*)d_in[0];
    const int*   bidx  = (const int*)d_in[1];
    const float* W_ih  = (const float*)d_in[2];
    const float* W_hh  = (const float*)d_in[3];
    const float* b_ih  = (const float*)d_in[4];
    const float* b_hh  = (const float*)d_in[5];
    float* out = (float*)d_out;

    int N = in_sizes[0] / D;

    // residency-safe persistent grid for barrier kernels
    int sms = 148, occ0 = 1, occ1 = 1;
    cudaDeviceGetAttribute(&sms, cudaDevAttrMultiProcessorCount, 0);
    cudaOccupancyMaxActiveBlocksPerMultiprocessor(&occ0, k_attn0, 256, 0);
    cudaOccupancyMaxActiveBlocksPerMultiprocessor(&occ1, k_attn, 256, 0);
    int occ = occ0 < occ1 ? occ0 : occ1;
    if (occ < 1) occ = 1;
    int agrid = sms * occ;
    if (agrid > ATTN_MAXGRID) agrid = ATTN_MAXGRID;

    k_pre<<<3072, 256>>>(W_ih, W_hh, b_ih, b_hh, bidx, N);
    k_scan<<<1, 512>>>();
    k_scatter<<<(N + SCHUNK - 1) / SCHUNK, 256>>>(bidx, N);

    k_attn0<<<agrid, 256>>>(feat, N);
    for (int step = 1; step < 3; step++) {
        dim3 grid(1024 / BN, 512 / BM, 4);   // split-K = 4
        k_gemm<<<grid, 256>>>();
        k_cellk<<<(G * D + 255) / 256, 256>>>();
        k_attn<<<agrid, 256>>>(N);
    }
    k_copyout<<<(G * 512 + 255) / 256, 256>>>(out);
}

// round 7
// speedup vs baseline: 3.7991x; 1.0403x over previous
#include <cuda_runtime.h>
#include <cuda_fp16.h>
#include <math.h>

#define G 512
#define D 256
#define MAXN 204800
#define GRID_CAP 1184

// ---------------- device scratch ----------------
__device__ float    g_Wc[1024 * 512];
__device__ float    g_biasc[1024];
__device__ int      g_counts[G];            // zero-init; k_scan resets after use
__device__ int      g_cursor[G];
__device__ int      g_perm[MAXN];
__device__ int      g_grank[MAXN];
__device__ float    g_xbuf[G * 512];        // [h | r(unnormalized)]
__device__ float    g_cbuf[G * D];
__device__ float    g_gates[G * 1024];
__device__ unsigned g_gmaxe[G];
__device__ float    g_gsum[G];
__device__ __half2  g_feat16[MAXN * (D/2)];
__device__ int          g_bar_count;
__device__ volatile int g_bar_gen;

__device__ __forceinline__ unsigned h2_as_u32(__half2 h) {
    union { __half2 h; unsigned u; } c; c.h = h; return c.u;
}
__device__ __forceinline__ __half2 u32_as_h2(unsigned u) {
    union { unsigned u; __half2 h; } c; c.u = u; return c.h;
}
__device__ __forceinline__ unsigned fenc(float f) {
    unsigned u = __float_as_uint(f);
    return (u & 0x80000000u) ? ~u : (u | 0x80000000u);
}
__device__ __forceinline__ float fdec(unsigned u) {
    return (u & 0x80000000u) ? __uint_as_float(u ^ 0x80000000u)
                             : __uint_as_float(~u);
}
#define ENC_NEG_INF 0x007FFFFFu

__device__ __forceinline__ float sigf(float x) { return 1.0f / (1.0f + expf(-x)); }

// ---------------- software grid barrier ----------------
__device__ __forceinline__ void grid_barrier() {
    __syncthreads();
    if (threadIdx.x == 0) {
        __threadfence();
        int gen = g_bar_gen;
        asm volatile("" ::: "memory");
        if (atomicAdd(&g_bar_count, 1) == (int)gridDim.x - 1) {
            g_bar_count = 0;
            __threadfence();
            atomicAdd((int*)&g_bar_gen, 1);
        } else {
            while (g_bar_gen == gen) __nanosleep(64);
        }
        __threadfence();
    }
    __syncthreads();
}

// ---------------- combined preamble ----------------
__global__ void __launch_bounds__(256) k_pre(const float* __restrict__ W_ih,
                                             const float* __restrict__ W_hh,
                                             const float* __restrict__ b_ih,
                                             const float* __restrict__ b_hh,
                                             const int* __restrict__ bidx, int N) {
    int b = blockIdx.x;
    if (b < 2048) {
        int i = b * 256 + threadIdx.x;
        int j = i >> 9, k = i & 511;
        float w = W_ih[i];
        if (k < D) w += W_hh[j * D + k];
        g_Wc[i] = w;
        if (i < 1024) g_biasc[i] = b_ih[i] + b_hh[i];
    } else if (b < 2560) {
        __shared__ int sh[G];
        for (int i = threadIdx.x; i < G; i += 256) sh[i] = 0;
        __syncthreads();
        for (int i = (b - 2048) * 256 + threadIdx.x; i < N; i += 512 * 256)
            atomicAdd(&sh[bidx[i]], 1);
        __syncthreads();
        for (int i = threadIdx.x; i < G; i += 256)
            if (sh[i]) atomicAdd(&g_counts[i], sh[i]);
    } else {                              // LSTM step 1 (zero state)
        int idx = (b - 2560) * 256 + threadIdx.x;
        int g = idx >> 8, d = idx & 255;
        float bi = b_ih[d]       + b_hh[d];
        float bg = b_ih[512 + d] + b_hh[512 + d];
        float bo = b_ih[768 + d] + b_hh[768 + d];
        float i_ = sigf(bi), gt = tanhf(bg), o_ = sigf(bo);
        float c = i_ * gt;
        float h = o_ * tanhf(c);
        g_cbuf[idx] = c;
        g_xbuf[g * 512 + d] = h;
        g_xbuf[g * 512 + D + d] = 0.0f;
        if (idx < G) { g_gmaxe[idx] = ENC_NEG_INF; g_gsum[idx] = 0.0f; }
#pragma unroll
        for (int k2 = 0; k2 < 4; k2++) g_gates[idx * 4 + k2] = 0.0f;
    }
}

__global__ void k_scan() {
    __shared__ int s[G];
    int t = threadIdx.x;
    s[t] = g_counts[t];
    __syncthreads();
    for (int o = 1; o < G; o <<= 1) {
        int v = 0;
        if (t >= o) v = s[t - o];
        __syncthreads();
        if (t >= o) s[t] += v;
        __syncthreads();
    }
    g_cursor[t] = s[t] - g_counts[t];
    g_counts[t] = 0;
}

#define SCHUNK 1024
__global__ void __launch_bounds__(256) k_scatter(const int* __restrict__ bidx, int N) {
    __shared__ int hist[G];
    int t = threadIdx.x;
    int b0 = blockIdx.x * SCHUNK;
    for (int i = t; i < G; i += 256) hist[i] = 0;
    __syncthreads();
#pragma unroll
    for (int k = 0; k < SCHUNK / 256; k++) {
        int i = b0 + k * 256 + t;
        if (i < N) atomicAdd(&hist[bidx[i]], 1);
    }
    __syncthreads();
    for (int gidx = t; gidx < G; gidx += 256) {
        int c = hist[gidx];
        if (c > 0) hist[gidx] = atomicAdd(&g_cursor[gidx], c);
    }
    __syncthreads();
#pragma unroll
    for (int k = 0; k < SCHUNK / 256; k++) {
        int i = b0 + k * 256 + t;
        if (i < N) {
            int g = bidx[i];
            int p = atomicAdd(&hist[g], 1);
            g_perm[p] = i;
            g_grank[p] = g;
        }
    }
}

// ---------------- GEMM: gates += q_star @ Wc^T, split-K=4, norm folded ---------
#define BM 64
#define BN 64
#define BK 32
__global__ void __launch_bounds__(256) k_gemm() {
    __shared__ float As[BK][BM + 4];
    __shared__ float Bs[BK][BN + 4];
    int tid = threadIdx.x;
    int bm = blockIdx.y * BM;
    int bn = blockIdx.x * BN;
    int k0 = blockIdx.z * 128;
    int lr = tid >> 2;
    int lc = (tid & 3) * 8;
    int tm = (tid >> 4) * 4;
    int tn = (tid & 15) * 4;
    float inv = 1.0f;
    if (blockIdx.z >= 2) inv = 1.0f / (g_gsum[bm + lr] + 1e-16f);
    float acc[4][4] = {};
    for (int kt = 0; kt < 128; kt += BK) {
        const float4* ap = (const float4*)(g_xbuf + (size_t)(bm + lr) * 512 + k0 + kt + lc);
        float4 a0 = ap[0], a1 = ap[1];
        a0.x *= inv; a0.y *= inv; a0.z *= inv; a0.w *= inv;
        a1.x *= inv; a1.y *= inv; a1.z *= inv; a1.w *= inv;
        const float4* bp = (const float4*)(g_Wc + (size_t)(bn + lr) * 512 + k0 + kt + lc);
        float4 b0 = bp[0], b1 = bp[1];
        __syncthreads();
        As[lc + 0][lr] = a0.x; As[lc + 1][lr] = a0.y; As[lc + 2][lr] = a0.z; As[lc + 3][lr] = a0.w;
        As[lc + 4][lr] = a1.x; As[lc + 5][lr] = a1.y; As[lc + 6][lr] = a1.z; As[lc + 7][lr] = a1.w;
        Bs[lc + 0][lr] = b0.x; Bs[lc + 1][lr] = b0.y; Bs[lc + 2][lr] = b0.z; Bs[lc + 3][lr] = b0.w;
        Bs[lc + 4][lr] = b1.x; Bs[lc + 5][lr] = b1.y; Bs[lc + 6][lr] = b1.z; Bs[lc + 7][lr] = b1.w;
        __syncthreads();
#pragma unroll
        for (int k = 0; k < BK; k++) {
            float4 av = *(const float4*)(&As[k][tm]);
            float4 bv = *(const float4*)(&Bs[k][tn]);
            float a[4] = {av.x, av.y, av.z, av.w};
            float b[4] = {bv.x, bv.y, bv.z, bv.w};
#pragma unroll
            for (int i = 0; i < 4; i++)
#pragma unroll
                for (int j = 0; j < 4; j++) acc[i][j] += a[i] * b[j];
        }
    }
#pragma unroll
    for (int i = 0; i < 4; i++)
#pragma unroll
        for (int j = 0; j < 4; j++)
            atomicAdd(&g_gates[(size_t)(bm + tm + i) * 1024 + bn + tn + j], acc[i][j]);
}

// ---------------- online softmax machinery ----------------
struct OState {
    int curg, pg;
    bool started_inside;
    float m, s, pm, ps;
    float acc[8], pacc[8], q[8];
};

__device__ __forceinline__ void load_q(int g, int lane, float* q) {
    const float4* qr = (const float4*)(g_xbuf + (size_t)g * 512);
    float4 q0 = qr[lane * 2], q1 = qr[lane * 2 + 1];
    q[0] = q0.x; q[1] = q0.y; q[2] = q0.z; q[3] = q0.w;
    q[4] = q1.x; q[5] = q1.y; q[6] = q1.z; q[7] = q1.w;
}

__device__ __forceinline__ void o_flush_global(int g, float m, float s,
                                               const float* acc, int lane) {
    float M = fdec(g_gmaxe[g]);
    float sc = __expf(m - M);
    float* base = g_xbuf + (size_t)g * 512 + D + lane * 8;
#pragma unroll
    for (int k = 0; k < 8; k++) atomicAdd(base + k, acc[k] * sc);
    if (lane == 0) atomicAdd(&g_gsum[g], s * sc);
}

// sole-owner interior segment: scale-invariant, no global-max rescale needed
__device__ __forceinline__ void o_flush_local(int g, float s, const float* acc, int lane) {
    float* base = g_xbuf + (size_t)g * 512 + D + lane * 8;
#pragma unroll
    for (int k = 0; k < 8; k++) atomicAdd(base + k, acc[k]);
    if (lane == 0) atomicAdd(&g_gsum[g], s);
}

__device__ __forceinline__ void o_update(float e, const float* f, OState& st) {
    if (e > st.m) {
        float sc = __expf(st.m - e);
        st.s *= sc;
#pragma unroll
        for (int k = 0; k < 8; k++) st.acc[k] *= sc;
        st.m = e;
    }
    float w = __expf(e - st.m);
    st.s += w;
#pragma unroll
    for (int k = 0; k < 8; k++) st.acc[k] += w * f[k];
}

__device__ __forceinline__ void o_boundary(OState& st, int newg, int lane) {
    if (st.started_inside) {
        o_flush_local(st.curg, st.s, st.acc, lane);
    } else {
        st.pg = st.curg; st.pm = st.m; st.ps = st.s;
#pragma unroll
        for (int k = 0; k < 8; k++) st.pacc[k] = st.acc[k];
    }
    st.started_inside = true;
    st.m = -1e30f; st.s = 0.0f;
#pragma unroll
    for (int k = 0; k < 8; k++) st.acc[k] = 0.0f;
    st.curg = newg;
    load_q(newg, lane, st.q);
}

__device__ __forceinline__ void o_finish(OState& st, int lane, bool valid) {
    if (valid && lane == 0) {
        atomicMax(&g_gmaxe[st.curg], fenc(st.m));
        if (st.pg >= 0) atomicMax(&g_gmaxe[st.pg], fenc(st.pm));
    }
    grid_barrier();
    if (valid) {
        o_flush_global(st.curg, st.m, st.s, st.acc, lane);
        if (st.pg >= 0) o_flush_global(st.pg, st.pm, st.ps, st.pacc, lane);
    }
}

__device__ __forceinline__ void expand16(uint4 fv, float* f) {
    float2 f0 = __half22float2(u32_as_h2(fv.x));
    float2 f1 = __half22float2(u32_as_h2(fv.y));
    float2 f2 = __half22float2(u32_as_h2(fv.z));
    float2 f3 = __half22float2(u32_as_h2(fv.w));
    f[0] = f0.x; f[1] = f0.y; f[2] = f1.x; f[3] = f1.y;
    f[4] = f2.x; f[5] = f2.y; f[6] = f3.x; f[7] = f3.y;
}

__device__ __forceinline__ float dot8(const float* f, const float* q) {
    return f[0]*q[0] + f[1]*q[1] + f[2]*q[2] + f[3]*q[3]
         + f[4]*q[4] + f[5]*q[5] + f[6]*q[6] + f[7]*q[7];
}

__device__ __forceinline__ float wreduce(float v) {
#pragma unroll
    for (int o = 16; o; o >>= 1) v += __shfl_xor_sync(0xffffffffu, v, o);
    return v;
}

__device__ __forceinline__ void warp_range(int N, int gsize, int bid, int warp,
                                           int& ws, int& we) {
    int per = (N + gsize - 1) / gsize;
    int bs = bid * per;
    int be = min(bs + per, N);
    int sub = (per + 7) >> 3;
    ws = min(bs + warp * sub, be);
    we = min(ws + sub, be);
}

// ---------------- attention step 1: fp32 gather + fp16 emit ----------------
__global__ void __launch_bounds__(256) k_attn0(const float* __restrict__ feat, int N) {
    int warp = threadIdx.x >> 5, lane = threadIdx.x & 31;
    int ws, we;
    warp_range(N, gridDim.x, blockIdx.x, warp, ws, we);
    OState st;
    st.pg = -1; st.started_inside = false;
    st.m = -1e30f; st.s = 0.0f; st.pm = 0.0f; st.ps = 0.0f;
#pragma unroll
    for (int k = 0; k < 8; k++) { st.acc[k] = 0.0f; st.pacc[k] = 0.0f; }
    bool valid = ws < we;
    if (valid) {
        st.curg = g_grank[ws];
        load_q(st.curg, lane, st.q);
        int r = ws;
        // 4-rank packs
        for (; r + 4 <= we; r += 4) {
            int g0 = g_grank[r], g1 = g_grank[r+1], g2 = g_grank[r+2], g3 = g_grank[r+3];
            float f4[4][8];
#pragma unroll
            for (int j = 0; j < 4; j++) {
                int n = g_perm[r + j];
                const float4* fr = (const float4*)(feat + (size_t)n * D);
                float4 a = fr[lane * 2], b = fr[lane * 2 + 1];
                f4[j][0] = a.x; f4[j][1] = a.y; f4[j][2] = a.z; f4[j][3] = a.w;
                f4[j][4] = b.x; f4[j][5] = b.y; f4[j][6] = b.z; f4[j][7] = b.w;
                uint4 o16;
                o16.x = h2_as_u32(__floats2half2_rn(a.x, a.y));
                o16.y = h2_as_u32(__floats2half2_rn(a.z, a.w));
                o16.z = h2_as_u32(__floats2half2_rn(b.x, b.y));
                o16.w = h2_as_u32(__floats2half2_rn(b.z, b.w));
                ((uint4*)(g_feat16 + (size_t)(r + j) * (D / 2)))[lane] = o16;
            }
            if ((g0 == st.curg) & (g1 == st.curg) & (g2 == st.curg) & (g3 == st.curg)) {
                float e4[4];
#pragma unroll
                for (int j = 0; j < 4; j++) e4[j] = dot8(f4[j], st.q);
#pragma unroll
                for (int o = 16; o; o >>= 1)
#pragma unroll
                    for (int j = 0; j < 4; j++)
                        e4[j] += __shfl_xor_sync(0xffffffffu, e4[j], o);
#pragma unroll
                for (int j = 0; j < 4; j++) o_update(e4[j], f4[j], st);
            } else {
                int gj[4] = {g0, g1, g2, g3};
#pragma unroll
                for (int j = 0; j < 4; j++) {
                    if (gj[j] != st.curg) o_boundary(st, gj[j], lane);
                    float e = wreduce(dot8(f4[j], st.q));
                    o_update(e, f4[j], st);
                }
            }
        }
        // tail
        for (; r < we; r++) {
            int grp = g_grank[r];
            int n = g_perm[r];
            const float4* fr = (const float4*)(feat + (size_t)n * D);
            float4 a = fr[lane * 2], b = fr[lane * 2 + 1];
            float f[8] = {a.x, a.y, a.z, a.w, b.x, b.y, b.z, b.w};
            uint4 o16;
            o16.x = h2_as_u32(__floats2half2_rn(a.x, a.y));
            o16.y = h2_as_u32(__floats2half2_rn(a.z, a.w));
            o16.z = h2_as_u32(__floats2half2_rn(b.x, b.y));
            o16.w = h2_as_u32(__floats2half2_rn(b.z, b.w));
            ((uint4*)(g_feat16 + (size_t)r * (D / 2)))[lane] = o16;
            if (grp != st.curg) o_boundary(st, grp, lane);
            float e = wreduce(dot8(f, st.q));
            o_update(e, f, st);
        }
    }
    o_finish(st, lane, valid);
}

// ---------------- attention steps 2-3: fused LSTM cell + fp16 attention -------
__global__ void __launch_bounds__(256) k_attn(int N) {
    // phase 0: LSTM cell (reads gates, writes h/c, zeros r/gates, resets max/sum)
    for (int idx = blockIdx.x * 256 + threadIdx.x; idx < G * D; idx += gridDim.x * 256) {
        int g = idx >> 8, d = idx & 255;
        int base = g * 1024;
        float gi = g_gates[base + d]       + g_biasc[d];
        float gf = g_gates[base + 256 + d] + g_biasc[256 + d];
        float gg = g_gates[base + 512 + d] + g_biasc[512 + d];
        float go = g_gates[base + 768 + d] + g_biasc[768 + d];
        float i_ = sigf(gi), f_ = sigf(gf), gt = tanhf(gg), o_ = sigf(go);
        float c = f_ * g_cbuf[idx] + i_ * gt;
        float h = o_ * tanhf(c);
        g_cbuf[idx] = c;
        g_xbuf[g * 512 + d] = h;
        g_xbuf[g * 512 + D + d] = 0.0f;
        g_gates[base + d] = 0.0f; g_gates[base + 256 + d] = 0.0f;
        g_gates[base + 512 + d] = 0.0f; g_gates[base + 768 + d] = 0.0f;
        if (idx < G) { g_gmaxe[idx] = ENC_NEG_INF; g_gsum[idx] = 0.0f; }
    }
    grid_barrier();

    int warp = threadIdx.x >> 5, lane = threadIdx.x & 31;
    int ws, we;
    warp_range(N, gridDim.x, blockIdx.x, warp, ws, we);
    OState st;
    st.pg = -1; st.started_inside = false;
    st.m = -1e30f; st.s = 0.0f; st.pm = 0.0f; st.ps = 0.0f;
#pragma unroll
    for (int k = 0; k < 8; k++) { st.acc[k] = 0.0f; st.pacc[k] = 0.0f; }
    bool valid = ws < we;
    if (valid) {
        st.curg = g_grank[ws];
        load_q(st.curg, lane, st.q);
        int r = ws;
        for (; r + 4 <= we; r += 4) {
            int g0 = g_grank[r], g1 = g_grank[r+1], g2 = g_grank[r+2], g3 = g_grank[r+3];
            uint4 fv0 = ((const uint4*)(g_feat16 + (size_t)(r+0) * (D/2)))[lane];
            uint4 fv1 = ((const uint4*)(g_feat16 + (size_t)(r+1) * (D/2)))[lane];
            uint4 fv2 = ((const uint4*)(g_feat16 + (size_t)(r+2) * (D/2)))[lane];
            uint4 fv3 = ((const uint4*)(g_feat16 + (size_t)(r+3) * (D/2)))[lane];
            float f4[4][8];
            expand16(fv0, f4[0]); expand16(fv1, f4[1]);
            expand16(fv2, f4[2]); expand16(fv3, f4[3]);
            if ((g0 == st.curg) & (g1 == st.curg) & (g2 == st.curg) & (g3 == st.curg)) {
                float e4[4];
#pragma unroll
                for (int j = 0; j < 4; j++) e4[j] = dot8(f4[j], st.q);
#pragma unroll
                for (int o = 16; o; o >>= 1)
#pragma unroll
                    for (int j = 0; j < 4; j++)
                        e4[j] += __shfl_xor_sync(0xffffffffu, e4[j], o);
#pragma unroll
                for (int j = 0; j < 4; j++) o_update(e4[j], f4[j], st);
            } else {
                int gj[4] = {g0, g1, g2, g3};
#pragma unroll
                for (int j = 0; j < 4; j++) {
                    if (gj[j] != st.curg) o_boundary(st, gj[j], lane);
                    float e = wreduce(dot8(f4[j], st.q));
                    o_update(e, f4[j], st);
                }
            }
        }
        for (; r < we; r++) {
            int grp = g_grank[r];
            uint4 fv = ((const uint4*)(g_feat16 + (size_t)r * (D/2)))[lane];
            float f[8];
            expand16(fv, f);
            if (grp != st.curg) o_boundary(st, grp, lane);
            float e = wreduce(dot8(f, st.q));
            o_update(e, f, st);
        }
    }
    o_finish(st, lane, valid);
}

// ---------------- copy result out (normalize r) ----------------
__global__ void k_copyout(float* __restrict__ out) {
    int i = blockIdx.x * blockDim.x + threadIdx.x;
    if (i < G * 512) {
        int g = i >> 9, d = i & 511;
        float v = g_xbuf[i];
        if (d >= D) v *= 1.0f / (g_gsum[g] + 1e-16f);
        out[i] = v;
    }
}

// ---------------- host launcher ----------------
extern "C" void kernel_launch(void* const* d_in, const int* in_sizes, int n_in,
                              void* d_out, int out_size) {
    const float* feat  = (const float*)d_in[0];
    const int*   bidx  = (const int*)d_in[1];
    const float* W_ih  = (const float*)d_in[2];
    const float* W_hh  = (const float*)d_in[3];
    const float* b_ih  = (const float*)d_in[4];
    const float* b_hh  = (const float*)d_in[5];
    float* out = (float*)d_out;

    int N = in_sizes[0] / D;

    int sms = 148, occ0 = 1, occ1 = 1;
    cudaDeviceGetAttribute(&sms, cudaDevAttrMultiProcessorCount, 0);
    cudaOccupancyMaxActiveBlocksPerMultiprocessor(&occ0, k_attn0, 256, 0);
    cudaOccupancyMaxActiveBlocksPerMultiprocessor(&occ1, k_attn, 256, 0);
    if (occ0 < 1) occ0 = 1;
    if (occ1 < 1) occ1 = 1;
    int agrid0 = sms * occ0; if (agrid0 > GRID_CAP) agrid0 = GRID_CAP;
    int agrid1 = sms * occ1; if (agrid1 > GRID_CAP) agrid1 = GRID_CAP;

    k_pre<<<3072, 256>>>(W_ih, W_hh, b_ih, b_hh, bidx, N);
    k_scan<<<1, 512>>>();
    k_scatter<<<(N + SCHUNK - 1) / SCHUNK, 256>>>(bidx, N);

    k_attn0<<<agrid0, 256>>>(feat, N);
    for (int step = 1; step < 3; step++) {
        dim3 grid(1024 / BN, 512 / BM, 4);
        k_gemm<<<grid, 256>>>();
        k_attn<<<agrid1, 256>>>(N);
    }
    k_copyout<<<(G * 512 + 255) / 256, 256>>>(out);
}

// round 8
// speedup vs baseline: 3.8739x; 1.0197x over previous
#include <cuda_runtime.h>
#include <cuda_fp16.h>
#include <math.h>

#define G 512
#define D 256
#define MAXN 204800
#define GRID_CAP 1184

// ---------------- device scratch ----------------
__device__ float    g_Wc[1024 * 512];
__device__ float    g_biasc[1024];
__device__ int      g_counts[G];            // zero-init; k_scan resets after use
__device__ int      g_cursor[G];
__device__ int      g_perm[MAXN];
__device__ int      g_grank[MAXN];
__device__ float    g_xbuf[G * 512];        // [h | r(unnormalized)]
__device__ float    g_cbuf[G * D];
__device__ float    g_gates[G * 1024];
__device__ unsigned g_gmaxe[G];
__device__ float    g_gsum[G];
__device__ __half2  g_feat16[MAXN * (D/2)];
__device__ int          g_bar_count;
__device__ volatile int g_bar_gen;

__device__ __forceinline__ unsigned h2_as_u32(__half2 h) {
    union { __half2 h; unsigned u; } c; c.h = h; return c.u;
}
__device__ __forceinline__ __half2 u32_as_h2(unsigned u) {
    union { unsigned u; __half2 h; } c; c.u = u; return c.h;
}
__device__ __forceinline__ unsigned fenc(float f) {
    unsigned u = __float_as_uint(f);
    return (u & 0x80000000u) ? ~u : (u | 0x80000000u);
}
__device__ __forceinline__ float fdec(unsigned u) {
    return (u & 0x80000000u) ? __uint_as_float(u ^ 0x80000000u)
                             : __uint_as_float(~u);
}
#define ENC_NEG_INF 0x007FFFFFu

__device__ __forceinline__ float sigf(float x) { return 1.0f / (1.0f + expf(-x)); }

// ---------------- software grid barrier ----------------
__device__ __forceinline__ void grid_barrier() {
    __syncthreads();
    if (threadIdx.x == 0) {
        __threadfence();
        int gen = g_bar_gen;
        asm volatile("" ::: "memory");
        if (atomicAdd(&g_bar_count, 1) == (int)gridDim.x - 1) {
            g_bar_count = 0;
            __threadfence();
            atomicAdd((int*)&g_bar_gen, 1);
        } else {
            while (g_bar_gen == gen) __nanosleep(64);
        }
        __threadfence();
    }
    __syncthreads();
}

// ---------------- combined preamble ----------------
__global__ void __launch_bounds__(256) k_pre(const float* __restrict__ W_ih,
                                             const float* __restrict__ W_hh,
                                             const float* __restrict__ b_ih,
                                             const float* __restrict__ b_hh,
                                             const int* __restrict__ bidx, int N) {
    int b = blockIdx.x;
    if (b < 2048) {
        int i = b * 256 + threadIdx.x;
        int j = i >> 9, k = i & 511;
        float w = W_ih[i];
        if (k < D) w += W_hh[j * D + k];
        g_Wc[i] = w;
        if (i < 1024) g_biasc[i] = b_ih[i] + b_hh[i];
    } else if (b < 2560) {
        __shared__ int sh[G];
        for (int i = threadIdx.x; i < G; i += 256) sh[i] = 0;
        __syncthreads();
        for (int i = (b - 2048) * 256 + threadIdx.x; i < N; i += 512 * 256)
            atomicAdd(&sh[bidx[i]], 1);
        __syncthreads();
        for (int i = threadIdx.x; i < G; i += 256)
            if (sh[i]) atomicAdd(&g_counts[i], sh[i]);
    } else {                              // LSTM step 1 (zero state)
        int idx = (b - 2560) * 256 + threadIdx.x;
        int g = idx >> 8, d = idx & 255;
        float bi = b_ih[d]       + b_hh[d];
        float bg = b_ih[512 + d] + b_hh[512 + d];
        float bo = b_ih[768 + d] + b_hh[768 + d];
        float i_ = sigf(bi), gt = tanhf(bg), o_ = sigf(bo);
        float c = i_ * gt;
        float h = o_ * tanhf(c);
        g_cbuf[idx] = c;
        g_xbuf[g * 512 + d] = h;
        g_xbuf[g * 512 + D + d] = 0.0f;
        if (idx < G) { g_gmaxe[idx] = ENC_NEG_INF; g_gsum[idx] = 0.0f; }
#pragma unroll
        for (int k2 = 0; k2 < 4; k2++) g_gates[idx * 4 + k2] = 0.0f;
    }
}

__global__ void k_scan() {
    __shared__ int s[G];
    int t = threadIdx.x;
    s[t] = g_counts[t];
    __syncthreads();
    for (int o = 1; o < G; o <<= 1) {
        int v = 0;
        if (t >= o) v = s[t - o];
        __syncthreads();
        if (t >= o) s[t] += v;
        __syncthreads();
    }
    g_cursor[t] = s[t] - g_counts[t];
    g_counts[t] = 0;
}

#define SCHUNK 1024
__global__ void __launch_bounds__(256) k_scatter(const int* __restrict__ bidx, int N) {
    __shared__ int hist[G];
    int t = threadIdx.x;
    int b0 = blockIdx.x * SCHUNK;
    for (int i = t; i < G; i += 256) hist[i] = 0;
    __syncthreads();
#pragma unroll
    for (int k = 0; k < SCHUNK / 256; k++) {
        int i = b0 + k * 256 + t;
        if (i < N) atomicAdd(&hist[bidx[i]], 1);
    }
    __syncthreads();
    for (int gidx = t; gidx < G; gidx += 256) {
        int c = hist[gidx];
        if (c > 0) hist[gidx] = atomicAdd(&g_cursor[gidx], c);
    }
    __syncthreads();
#pragma unroll
    for (int k = 0; k < SCHUNK / 256; k++) {
        int i = b0 + k * 256 + t;
        if (i < N) {
            int g = bidx[i];
            int p = atomicAdd(&hist[g], 1);
            g_perm[p] = i;
            g_grank[p] = g;
        }
    }
}

// ---------------- GEMM: gates += q_star @ Wc^T, split-K=4, norm folded ---------
#define BM 64
#define BN 64
#define BK 32
__global__ void __launch_bounds__(256) k_gemm() {
    __shared__ float As[BK][BM + 4];
    __shared__ float Bs[BK][BN + 4];
    int tid = threadIdx.x;
    int bm = blockIdx.y * BM;
    int bn = blockIdx.x * BN;
    int k0 = blockIdx.z * 128;
    int lr = tid >> 2;
    int lc = (tid & 3) * 8;
    int tm = (tid >> 4) * 4;
    int tn = (tid & 15) * 4;
    float inv = 1.0f;
    if (blockIdx.z >= 2) inv = 1.0f / (g_gsum[bm + lr] + 1e-16f);
    float acc[4][4] = {};
    for (int kt = 0; kt < 128; kt += BK) {
        const float4* ap = (const float4*)(g_xbuf + (size_t)(bm + lr) * 512 + k0 + kt + lc);
        float4 a0 = ap[0], a1 = ap[1];
        a0.x *= inv; a0.y *= inv; a0.z *= inv; a0.w *= inv;
        a1.x *= inv; a1.y *= inv; a1.z *= inv; a1.w *= inv;
        const float4* bp = (const float4*)(g_Wc + (size_t)(bn + lr) * 512 + k0 + kt + lc);
        float4 b0 = bp[0], b1 = bp[1];
        __syncthreads();
        As[lc + 0][lr] = a0.x; As[lc + 1][lr] = a0.y; As[lc + 2][lr] = a0.z; As[lc + 3][lr] = a0.w;
        As[lc + 4][lr] = a1.x; As[lc + 5][lr] = a1.y; As[lc + 6][lr] = a1.z; As[lc + 7][lr] = a1.w;
        Bs[lc + 0][lr] = b0.x; Bs[lc + 1][lr] = b0.y; Bs[lc + 2][lr] = b0.z; Bs[lc + 3][lr] = b0.w;
        Bs[lc + 4][lr] = b1.x; Bs[lc + 5][lr] = b1.y; Bs[lc + 6][lr] = b1.z; Bs[lc + 7][lr] = b1.w;
        __syncthreads();
#pragma unroll
        for (int k = 0; k < BK; k++) {
            float4 av = *(const float4*)(&As[k][tm]);
            float4 bv = *(const float4*)(&Bs[k][tn]);
            float a[4] = {av.x, av.y, av.z, av.w};
            float b[4] = {bv.x, bv.y, bv.z, bv.w};
#pragma unroll
            for (int i = 0; i < 4; i++)
#pragma unroll
                for (int j = 0; j < 4; j++) acc[i][j] += a[i] * b[j];
        }
    }
#pragma unroll
    for (int i = 0; i < 4; i++)
#pragma unroll
        for (int j = 0; j < 4; j++)
            atomicAdd(&g_gates[(size_t)(bm + tm + i) * 1024 + bn + tn + j], acc[i][j]);
}

// ---------------- online softmax machinery (register-light) ----------------
__device__ __forceinline__ void load_q(int g, int lane, float* q) {
    const float4* qr = (const float4*)(g_xbuf + (size_t)g * 512);
    float4 q0 = qr[lane * 2], q1 = qr[lane * 2 + 1];
    q[0] = q0.x; q[1] = q0.y; q[2] = q0.z; q[3] = q0.w;
    q[4] = q1.x; q[5] = q1.y; q[6] = q1.z; q[7] = q1.w;
}

__device__ __forceinline__ void expand16(uint4 fv, float* f) {
    float2 f0 = __half22float2(u32_as_h2(fv.x));
    float2 f1 = __half22float2(u32_as_h2(fv.y));
    float2 f2 = __half22float2(u32_as_h2(fv.z));
    float2 f3 = __half22float2(u32_as_h2(fv.w));
    f[0] = f0.x; f[1] = f0.y; f[2] = f1.x; f[3] = f1.y;
    f[4] = f2.x; f[5] = f2.y; f[6] = f3.x; f[7] = f3.y;
}

__device__ __forceinline__ float dot8(const float* f, const float* q) {
    return f[0]*q[0] + f[1]*q[1] + f[2]*q[2] + f[3]*q[3]
         + f[4]*q[4] + f[5]*q[5] + f[6]*q[6] + f[7]*q[7];
}

__device__ __forceinline__ float wreduce(float v) {
#pragma unroll
    for (int o = 16; o; o >>= 1) v += __shfl_xor_sync(0xffffffffu, v, o);
    return v;
}

__device__ __forceinline__ void o_flush_global(int g, float m, float s,
                                               const float* acc, int lane) {
    float M = fdec(g_gmaxe[g]);
    float sc = __expf(m - M);
    float* base = g_xbuf + (size_t)g * 512 + D + lane * 8;
#pragma unroll
    for (int k = 0; k < 8; k++) atomicAdd(base + k, acc[k] * sc);
    if (lane == 0) atomicAdd(&g_gsum[g], s * sc);
}

// sole-owner interior segment: scale-invariant, no global-max rescale needed
__device__ __forceinline__ void o_flush_local(int g, float s, const float* acc, int lane) {
    float* base = g_xbuf + (size_t)g * 512 + D + lane * 8;
#pragma unroll
    for (int k = 0; k < 8; k++) atomicAdd(base + k, acc[k]);
    if (lane == 0) atomicAdd(&g_gsum[g], s);
}

__device__ __forceinline__ void o_update(float e, const float* f,
                                         float& m, float& s, float* acc) {
    if (e > m) {
        float sc = __expf(m - e);
        s *= sc;
#pragma unroll
        for (int k = 0; k < 8; k++) acc[k] *= sc;
        m = e;
    }
    float w = __expf(e - m);
    s += w;
#pragma unroll
    for (int k = 0; k < 8; k++) acc[k] += w * f[k];
}

__device__ __forceinline__ void warp_range(int N, int gsize, int bid, int warp,
                                           int& ws, int& we) {
    int per = (N + gsize - 1) / gsize;
    int bs = bid * per;
    int be = min(bs + per, N);
    int sub = (per + 7) >> 3;
    ws = min(bs + warp * sub, be);
    we = min(ws + sub, be);
}

// Core attention loop. FIRST=1: gather fp32 via perm, emit fp16 cache.
// pacc spill state lives in shared memory (rarely touched).
template <int FIRST>
__device__ __forceinline__ void attn_core(const float* __restrict__ feat, int N) {
    __shared__ float s_pacc[8][32 * 8];
    int warp = threadIdx.x >> 5, lane = threadIdx.x & 31;
    int ws, we;
    warp_range(N, gridDim.x, blockIdx.x, warp, ws, we);
    bool valid = ws < we;

    int curg = 0, pg = -1;
    bool started_inside = false;
    float m = -1e30f, s = 0.0f, pm = 0.0f, ps = 0.0f;
    float acc[8] = {};
    float q[8];

    // packed fp16 row loader (emits cache when FIRST)
    auto load_row = [&](int r) -> uint4 {
        if (FIRST) {
            int n = g_perm[r];
            const float4* fr = (const float4*)(feat + (size_t)n * D);
            float4 a = fr[lane * 2], b = fr[lane * 2 + 1];
            uint4 o;
            o.x = h2_as_u32(__floats2half2_rn(a.x, a.y));
            o.y = h2_as_u32(__floats2half2_rn(a.z, a.w));
            o.z = h2_as_u32(__floats2half2_rn(b.x, b.y));
            o.w = h2_as_u32(__floats2half2_rn(b.z, b.w));
            ((uint4*)(g_feat16 + (size_t)r * (D / 2)))[lane] = o;
            return o;
        } else {
            return ((const uint4*)(g_feat16 + (size_t)r * (D / 2)))[lane];
        }
    };

    auto boundary = [&](int newg) {
        if (started_inside) {
            o_flush_local(curg, s, acc, lane);
        } else {
            pg = curg; pm = m; ps = s;
#pragma unroll
            for (int k = 0; k < 8; k++) s_pacc[warp][lane * 8 + k] = acc[k];
        }
        started_inside = true;
        m = -1e30f; s = 0.0f;
#pragma unroll
        for (int k = 0; k < 8; k++) acc[k] = 0.0f;
        curg = newg;
        load_q(newg, lane, q);
    };

    if (valid) {
        curg = g_grank[ws];
        load_q(curg, lane, q);
        int r = ws;
        for (; r + 4 <= we; r += 4) {
            int g4[4];
#pragma unroll
            for (int j = 0; j < 4; j++) g4[j] = g_grank[r + j];
            uint4 fv4[4];
#pragma unroll
            for (int j = 0; j < 4; j++) fv4[j] = load_row(r + j);
            bool uni = (g4[0] == curg) & (g4[1] == curg) & (g4[2] == curg) & (g4[3] == curg);
            if (uni) {
                float e4[4];
#pragma unroll
                for (int j = 0; j < 4; j++) {
                    float f[8]; expand16(fv4[j], f);
                    e4[j] = dot8(f, q);
                }
#pragma unroll
                for (int o = 16; o; o >>= 1)
#pragma unroll
                    for (int j = 0; j < 4; j++)
                        e4[j] += __shfl_xor_sync(0xffffffffu, e4[j], o);
#pragma unroll
                for (int j = 0; j < 4; j++) {
                    float f[8]; expand16(fv4[j], f);
                    o_update(e4[j], f, m, s, acc);
                }
            } else {
#pragma unroll
                for (int j = 0; j < 4; j++) {
                    if (g4[j] != curg) boundary(g4[j]);
                    float f[8]; expand16(fv4[j], f);
                    float e = wreduce(dot8(f, q));
                    o_update(e, f, m, s, acc);
                }
            }
        }
        for (; r < we; r++) {
            int grp = g_grank[r];
            uint4 fv = load_row(r);
            if (grp != curg) boundary(grp);
            float f[8]; expand16(fv, f);
            float e = wreduce(dot8(f, q));
            o_update(e, f, m, s, acc);
        }
        if (lane == 0) {
            atomicMax(&g_gmaxe[curg], fenc(m));
            if (pg >= 0) atomicMax(&g_gmaxe[pg], fenc(pm));
        }
    }
    grid_barrier();
    if (valid) {
        o_flush_global(curg, m, s, acc, lane);
        if (pg >= 0) {
            float t[8];
#pragma unroll
            for (int k = 0; k < 8; k++) t[k] = s_pacc[warp][lane * 8 + k];
            o_flush_global(pg, pm, ps, t, lane);
        }
    }
}

// ---------------- attention step 1 ----------------
__global__ void __launch_bounds__(256, 4) k_attn0(const float* __restrict__ feat, int N) {
    attn_core<1>(feat, N);
}

// ---------------- attention steps 2-3 (fused LSTM cell phase) ----------------
__global__ void __launch_bounds__(256, 4) k_attn(int N) {
    for (int idx = blockIdx.x * 256 + threadIdx.x; idx < G * D; idx += gridDim.x * 256) {
        int g = idx >> 8, d = idx & 255;
        int base = g * 1024;
        float gi = g_gates[base + d]       + g_biasc[d];
        float gf = g_gates[base + 256 + d] + g_biasc[256 + d];
        float gg = g_gates[base + 512 + d] + g_biasc[512 + d];
        float go = g_gates[base + 768 + d] + g_biasc[768 + d];
        float i_ = sigf(gi), f_ = sigf(gf), gt = tanhf(gg), o_ = sigf(go);
        float c = f_ * g_cbuf[idx] + i_ * gt;
        float h = o_ * tanhf(c);
        g_cbuf[idx] = c;
        g_xbuf[g * 512 + d] = h;
        g_xbuf[g * 512 + D + d] = 0.0f;
        g_gates[base + d] = 0.0f; g_gates[base + 256 + d] = 0.0f;
        g_gates[base + 512 + d] = 0.0f; g_gates[base + 768 + d] = 0.0f;
        if (idx < G) { g_gmaxe[idx] = ENC_NEG_INF; g_gsum[idx] = 0.0f; }
    }
    grid_barrier();
    attn_core<0>(nullptr, N);
}

// ---------------- copy result out (normalize r) ----------------
__global__ void k_copyout(float* __restrict__ out) {
    int i = blockIdx.x * blockDim.x + threadIdx.x;
    if (i < G * 512) {
        int g = i >> 9, d = i & 511;
        float v = g_xbuf[i];
        if (d >= D) v *= 1.0f / (g_gsum[g] + 1e-16f);
        out[i] = v;
    }
}

// ---------------- host launcher ----------------
extern "C" void kernel_launch(void* const* d_in, const int* in_sizes, int n_in,
                              void* d_out, int out_size) {
    const float* feat  = (const float*)d_in[0];
    const int*   bidx  = (const int*)d_in[1];
    const float* W_ih  = (const float*)d_in[2];
    const float* W_hh  = (const float*)d_in[3];
    const float* b_ih  = (const float*)d_in[4];
    const float* b_hh  = (const float*)d_in[5];
    float* out = (float*)d_out;

    int N = in_sizes[0] / D;

    int sms = 148, occ0 = 1, occ1 = 1;
    cudaDeviceGetAttribute(&sms, cudaDevAttrMultiProcessorCount, 0);
    cudaOccupancyMaxActiveBlocksPerMultiprocessor(&occ0, k_attn0, 256, 0);
    cudaOccupancyMaxActiveBlocksPerMultiprocessor(&occ1, k_attn, 256, 0);
    if (occ0 < 1) occ0 = 1;
    if (occ1 < 1) occ1 = 1;
    int agrid0 = sms * occ0; if (agrid0 > GRID_CAP) agrid0 = GRID_CAP;
    int agrid1 = sms * occ1; if (agrid1 > GRID_CAP) agrid1 = GRID_CAP;

    k_pre<<<3072, 256>>>(W_ih, W_hh, b_ih, b_hh, bidx, N);
    k_scan<<<1, 512>>>();
    k_scatter<<<(N + SCHUNK - 1) / SCHUNK, 256>>>(bidx, N);

    k_attn0<<<agrid0, 256>>>(feat, N);
    for (int step = 1; step < 3; step++) {
        dim3 grid(1024 / BN, 512 / BM, 4);
        k_gemm<<<grid, 256>>>();
        k_attn<<<agrid1, 256>>>(N);
    }
    k_copyout<<<(G * 512 + 255) / 256, 256>>>(out);
}